// round 7
// baseline (speedup 1.0000x reference)
#include <cuda_runtime.h>
#include <cuda_bf16.h>
#include <math.h>
#include <stdint.h>

// Problem constants
#define BB 2
#define SS 4096
#define DD 1024
#define HH 16
#define HDIM 64
#define MM 512
#define LL 1024          // 2*MM
#define HID 2816
#define NSTEP 8          // SS/MM

// ---------------- scratch (device globals; no allocation allowed) ----------------
__device__ float g_Y  [BB * SS * DD];
__device__ float g_Q  [BB * LL * DD];
__device__ float g_K  [BB * LL * DD];
__device__ float g_V  [BB * LL * DD];
__device__ float g_OM2[BB * MM * DD];
__device__ float g_HN [BB * MM * DD];
__device__ float g_H1 [BB * MM * HID];
__device__ float g_H3 [BB * MM * HID];
__device__ float g_OMN[BB * MM * DD];

// packed bf16 hi/lo weight tiles: (n_blk 64 x k_chunk 32), n-major, 80B row stride.
#define TILE_B 5120
#define PK_SQ  (512 * 2560)
#define PK_W13 (1408 * 2560)
#define PK_W2  (1408 * 2560)
#define PK_TOTAL (7*PK_SQ + 2*PK_W13 + PK_W2)
__device__ __align__(256) __nv_bfloat16 g_pk_hi[PK_TOTAL];
__device__ __align__(256) __nv_bfloat16 g_pk_lo[PK_TOTAL];

#define OFF_WQ  0
#define OFF_WK  (1*PK_SQ)
#define OFF_WV  (2*PK_SQ)
#define OFF_WM  (3*PK_SQ)
#define OFF_WKM (4*PK_SQ)
#define OFF_WVM (5*PK_SQ)
#define OFF_WO  (6*PK_SQ)
#define OFF_W1  (7*PK_SQ)
#define OFF_W3  (7*PK_SQ + PK_W13)
#define OFF_W2  (7*PK_SQ + 2*PK_W13)

// ---------------- mma / ldmatrix helpers (baseline PTX) ----------------
__device__ __forceinline__ void mma16816(float* c, const uint32_t* a, const uint32_t* b) {
    asm volatile(
        "mma.sync.aligned.m16n8k16.row.col.f32.bf16.bf16.f32 "
        "{%0,%1,%2,%3}, {%4,%5,%6,%7}, {%8,%9}, {%0,%1,%2,%3};"
        : "+f"(c[0]), "+f"(c[1]), "+f"(c[2]), "+f"(c[3])
        : "r"(a[0]), "r"(a[1]), "r"(a[2]), "r"(a[3]), "r"(b[0]), "r"(b[1]));
}
__device__ __forceinline__ void ldsm4(uint32_t* r, uint32_t addr) {
    asm volatile("ldmatrix.sync.aligned.m8n8.x4.shared.b16 {%0,%1,%2,%3}, [%4];"
        : "=r"(r[0]), "=r"(r[1]), "=r"(r[2]), "=r"(r[3]) : "r"(addr));
}
__device__ __forceinline__ void ldsm4t(uint32_t* r, uint32_t addr) {
    asm volatile("ldmatrix.sync.aligned.m8n8.x4.trans.shared.b16 {%0,%1,%2,%3}, [%4];"
        : "=r"(r[0]), "=r"(r[1]), "=r"(r[2]), "=r"(r[3]) : "r"(addr));
}
__device__ __forceinline__ uint32_t smem_u32(const void* p) {
    uint32_t a;
    asm("{ .reg .u64 t; cvta.to.shared.u64 t, %1; cvt.u32.u64 %0, t; }" : "=r"(a) : "l"(p));
    return a;
}
__device__ __forceinline__ void splitpack(float x, float y, uint32_t& hi, uint32_t& lo) {
    __nv_bfloat16 hx = __float2bfloat16_rn(x);
    __nv_bfloat16 hy = __float2bfloat16_rn(y);
    __nv_bfloat16 lx = __float2bfloat16_rn(x - __bfloat162float(hx));
    __nv_bfloat16 ly = __float2bfloat16_rn(y - __bfloat162float(hy));
    hi = (uint32_t)__bfloat16_as_ushort(hx) | ((uint32_t)__bfloat16_as_ushort(hy) << 16);
    lo = (uint32_t)__bfloat16_as_ushort(lx) | ((uint32_t)__bfloat16_as_ushort(ly) << 16);
}

// ================= weight repack: fp32 [K,N] -> n-major bf16 hi/lo tiles =================
__device__ __forceinline__ void repack_body(
    const float* __restrict__ W, __nv_bfloat16* __restrict__ Wh,
    __nv_bfloat16* __restrict__ Wl, int N, int KC, int kc, int nb)
{
    __shared__ unsigned char sh[TILE_B];
    __shared__ unsigned char sl[TILE_B];
    for (int e = threadIdx.x; e < 2048; e += 256) {
        int n_l = e & 63, k_l = e >> 6;
        float v = W[(long long)(kc * 32 + k_l) * N + nb * 64 + n_l];
        __nv_bfloat16 h = __float2bfloat16_rn(v);
        __nv_bfloat16 l = __float2bfloat16_rn(v - __bfloat162float(h));
        unsigned off = (unsigned)(n_l * 80 + k_l * 2);
        *(__nv_bfloat16*)(sh + off) = h;
        *(__nv_bfloat16*)(sl + off) = l;
    }
    __syncthreads();
    long long tb = ((long long)nb * KC + kc) * TILE_B;
    uint4* dh = (uint4*)((char*)Wh + tb);
    uint4* dl = (uint4*)((char*)Wl + tb);
    int t = threadIdx.x;
    dh[t] = ((uint4*)sh)[t];
    dl[t] = ((uint4*)sl)[t];
    if (t < 64) {
        dh[256 + t] = ((uint4*)sh)[256 + t];
        dl[256 + t] = ((uint4*)sl)[256 + t];
    }
}

__global__ __launch_bounds__(256) void repack_sq7(
    const float* w0, const float* w1, const float* w2, const float* w3,
    const float* w4, const float* w5, const float* w6,
    __nv_bfloat16* PH, __nv_bfloat16* PL)
{
    int z = blockIdx.z;
    const float* W = (z == 0) ? w0 : (z == 1) ? w1 : (z == 2) ? w2 :
                     (z == 3) ? w3 : (z == 4) ? w4 : (z == 5) ? w5 : w6;
    repack_body(W, PH + (long long)z * PK_SQ, PL + (long long)z * PK_SQ,
                DD, 32, blockIdx.x, blockIdx.y);
}
__global__ __launch_bounds__(256) void repack_w13(
    const float* w1, const float* w3, __nv_bfloat16* PH, __nv_bfloat16* PL)
{
    int z = blockIdx.z;
    repack_body(z ? w3 : w1, PH + OFF_W1 + (long long)z * PK_W13,
                PL + OFF_W1 + (long long)z * PK_W13, HID, 32, blockIdx.x, blockIdx.y);
}
__global__ __launch_bounds__(256) void repack_one(
    const float* W, __nv_bfloat16* Wh, __nv_bfloat16* Wl, int N)
{
    repack_body(W, Wh, Wl, N, gridDim.x, blockIdx.x, blockIdx.y);
}

// ================= mma.sync GEMM, CTA 128x128, warp 32x64, double-buffered =================
// C[row,col] (+)= A[row,:] @ B, bf16 hi/lo split (AhBh + AhBl + AlBh, fp32 acc).
// BK=32, 256 threads = 8 warps: mw = wid&3 (4 x 32 rows), nw = wid>>2 (2 x 64 cols).
// B smem = two packed 64x32 tiles concatenated (row stride 80B, rows 0..127).
#define SA_H 0
#define SA_L 10240
#define SB_H 20480
#define SB_L 30720
#define GBUF 40960

__global__ __launch_bounds__(256, 1) void mma_gemm(
    const float* __restrict__ A,
    const __nv_bfloat16* __restrict__ Bh0, const __nv_bfloat16* __restrict__ Bl0,
    const __nv_bfloat16* __restrict__ Bh1, const __nv_bfloat16* __restrict__ Bl1,
    const __nv_bfloat16* __restrict__ Bh2, const __nv_bfloat16* __restrict__ Bl2,
    float* __restrict__ C0, float* __restrict__ C1, float* __restrict__ C2,
    int Nper, int K, int nbper,
    long long a_bs, int a_off, int Mchunk,
    long long c_bs, int c_off, int acc)
{
    extern __shared__ __align__(16) unsigned char smem[];
    uint32_t sb = smem_u32(smem);

    int tid = threadIdx.x;
    int wid = tid >> 5, lane = tid & 31;
    int g = lane >> 2, q = lane & 3;
    int mw = wid & 3, nw = wid >> 2;
    int rowin = lane & 7, l8 = (lane >> 3) & 1, l16 = (lane >> 4) & 1;

    int sel = blockIdx.x / nbper;
    int n_blk = blockIdx.x - sel * nbper;        // 128-col block index
    int block_n = n_blk * 128;
    int block_m = blockIdx.y * 128;
    const __nv_bfloat16* Bh = (sel == 0) ? Bh0 : ((sel == 1) ? Bh1 : Bh2);
    const __nv_bfloat16* Bl = (sel == 0) ? Bl0 : ((sel == 1) ? Bl1 : Bl2);
    float*               C  = (sel == 0) ? C0  : ((sel == 1) ? C1  : C2);

    int nk = K >> 5;

    // A loader: 4 float4/thread, rows 0..127, 80B smem row stride
    const float* aptr[4];
    unsigned     ast_off[4];
    #pragma unroll
    for (int j = 0; j < 4; j++) {
        int f = tid + j * 256;
        int row = f >> 3, c4 = f & 7;
        int gr = block_m + row;
        aptr[j] = A + (long long)(gr / Mchunk) * a_bs
                    + (long long)((gr % Mchunk) + a_off) * K + c4 * 4;
        ast_off[j] = (unsigned)(row * 80 + c4 * 8);
    }
    // B loaders: two 64-row tiles per chunk (n_blk*2 and n_blk*2+1)
    const char* bh_t0 = (const char*)Bh + (long long)(2 * n_blk)     * nk * TILE_B;
    const char* bh_t1 = (const char*)Bh + (long long)(2 * n_blk + 1) * nk * TILE_B;
    const char* bl_t0 = (const char*)Bl + (long long)(2 * n_blk)     * nk * TILE_B;
    const char* bl_t1 = (const char*)Bl + (long long)(2 * n_blk + 1) * nk * TILE_B;

    // ldmatrix fragment offsets
    unsigned a_frag_off[2];
    #pragma unroll
    for (int i = 0; i < 2; i++)
        a_frag_off[i] = (unsigned)((mw * 32 + i * 16 + rowin + l8 * 8) * 80 + l16 * 16);
    unsigned b_frag_off[4];
    #pragma unroll
    for (int jp = 0; jp < 4; jp++)
        b_frag_off[jp] = (unsigned)((nw * 64 + jp * 16 + rowin + l16 * 8) * 80 + l8 * 16);

    float c[2][8][4];
    #pragma unroll
    for (int i = 0; i < 2; i++)
        #pragma unroll
        for (int j = 0; j < 8; j++)
            #pragma unroll
            for (int e = 0; e < 4; e++) c[i][j][e] = 0.f;

    // prefetch chunk 0
    float4 pa[4];
    uint4 ph[4], pl[4];
    #pragma unroll
    for (int j = 0; j < 4; j++) pa[j] = *(const float4*)(aptr[j]);
    ph[0] = *(const uint4*)(bh_t0 + tid * 16);
    ph[2] = *(const uint4*)(bh_t1 + tid * 16);
    pl[0] = *(const uint4*)(bl_t0 + tid * 16);
    pl[2] = *(const uint4*)(bl_t1 + tid * 16);
    if (tid < 64) {
        ph[1] = *(const uint4*)(bh_t0 + (256 + tid) * 16);
        ph[3] = *(const uint4*)(bh_t1 + (256 + tid) * 16);
        pl[1] = *(const uint4*)(bl_t0 + (256 + tid) * 16);
        pl[3] = *(const uint4*)(bl_t1 + (256 + tid) * 16);
    }

    // store chunk 0 into buffer 0
    #pragma unroll
    for (int j = 0; j < 4; j++) {
        float4 v = pa[j];
        uint2 hv, lv;
        splitpack(v.x, v.y, hv.x, lv.x);
        splitpack(v.z, v.w, hv.y, lv.y);
        *(uint2*)(smem + SA_H + ast_off[j]) = hv;
        *(uint2*)(smem + SA_L + ast_off[j]) = lv;
    }
    *(uint4*)(smem + SB_H + tid * 16)        = ph[0];
    *(uint4*)(smem + SB_H + 5120 + tid * 16) = ph[2];
    *(uint4*)(smem + SB_L + tid * 16)        = pl[0];
    *(uint4*)(smem + SB_L + 5120 + tid * 16) = pl[2];
    if (tid < 64) {
        *(uint4*)(smem + SB_H + (256 + tid) * 16)        = ph[1];
        *(uint4*)(smem + SB_H + 5120 + (256 + tid) * 16) = ph[3];
        *(uint4*)(smem + SB_L + (256 + tid) * 16)        = pl[1];
        *(uint4*)(smem + SB_L + 5120 + (256 + tid) * 16) = pl[3];
    }
    __syncthreads();

    int cur = 0;
    for (int it = 0; it < nk; it++) {
        bool hn = (it + 1 < nk);
        if (hn) {
            #pragma unroll
            for (int j = 0; j < 4; j++) pa[j] = *(const float4*)(aptr[j] + (it + 1) * 32);
            long long bo = (long long)(it + 1) * TILE_B;
            ph[0] = *(const uint4*)(bh_t0 + bo + tid * 16);
            ph[2] = *(const uint4*)(bh_t1 + bo + tid * 16);
            pl[0] = *(const uint4*)(bl_t0 + bo + tid * 16);
            pl[2] = *(const uint4*)(bl_t1 + bo + tid * 16);
            if (tid < 64) {
                ph[1] = *(const uint4*)(bh_t0 + bo + (256 + tid) * 16);
                ph[3] = *(const uint4*)(bh_t1 + bo + (256 + tid) * 16);
                pl[1] = *(const uint4*)(bl_t0 + bo + (256 + tid) * 16);
                pl[3] = *(const uint4*)(bl_t1 + bo + (256 + tid) * 16);
            }
        }

        uint32_t abh = sb + cur * GBUF + SA_H;
        uint32_t abl = sb + cur * GBUF + SA_L;
        uint32_t bbh = sb + cur * GBUF + SB_H;
        uint32_t bbl = sb + cur * GBUF + SB_L;
        #pragma unroll
        for (int kk = 0; kk < 2; kk++) {
            int kb = kk * 32;
            uint32_t ah[2][4], al[2][4];
            #pragma unroll
            for (int i = 0; i < 2; i++) {
                ldsm4(ah[i], abh + a_frag_off[i] + kb);
                ldsm4(al[i], abl + a_frag_off[i] + kb);
            }
            #pragma unroll
            for (int jp = 0; jp < 4; jp++) {
                uint32_t bh[4], bl[4];
                ldsm4(bh, bbh + b_frag_off[jp] + kb);
                ldsm4(bl, bbl + b_frag_off[jp] + kb);
                #pragma unroll
                for (int i = 0; i < 2; i++) {
                    mma16816(c[i][jp*2],   ah[i], &bh[0]);
                    mma16816(c[i][jp*2],   ah[i], &bl[0]);
                    mma16816(c[i][jp*2],   al[i], &bh[0]);
                    mma16816(c[i][jp*2+1], ah[i], &bh[2]);
                    mma16816(c[i][jp*2+1], ah[i], &bl[2]);
                    mma16816(c[i][jp*2+1], al[i], &bh[2]);
                }
            }
        }

        if (hn) {
            uint32_t base = (cur ^ 1) * GBUF;
            #pragma unroll
            for (int j = 0; j < 4; j++) {
                float4 v = pa[j];
                uint2 hv, lv;
                splitpack(v.x, v.y, hv.x, lv.x);
                splitpack(v.z, v.w, hv.y, lv.y);
                *(uint2*)(smem + base + SA_H + ast_off[j]) = hv;
                *(uint2*)(smem + base + SA_L + ast_off[j]) = lv;
            }
            *(uint4*)(smem + base + SB_H + tid * 16)        = ph[0];
            *(uint4*)(smem + base + SB_H + 5120 + tid * 16) = ph[2];
            *(uint4*)(smem + base + SB_L + tid * 16)        = pl[0];
            *(uint4*)(smem + base + SB_L + 5120 + tid * 16) = pl[2];
            if (tid < 64) {
                *(uint4*)(smem + base + SB_H + (256 + tid) * 16)        = ph[1];
                *(uint4*)(smem + base + SB_H + 5120 + (256 + tid) * 16) = ph[3];
                *(uint4*)(smem + base + SB_L + (256 + tid) * 16)        = pl[1];
                *(uint4*)(smem + base + SB_L + 5120 + (256 + tid) * 16) = pl[3];
            }
            __syncthreads();
            cur ^= 1;
        }
    }

    // epilogue
    #pragma unroll
    for (int i = 0; i < 2; i++) {
        int row0 = block_m + mw * 32 + i * 16 + g;
        #pragma unroll
        for (int half = 0; half < 2; half++) {
            int gr = row0 + half * 8;
            float* crow = C + (long long)(gr / Mchunk) * c_bs
                            + (long long)((gr % Mchunk) + c_off) * Nper + block_n;
            #pragma unroll
            for (int j = 0; j < 8; j++) {
                int col = nw * 64 + j * 8 + 2 * q;
                float2 v;
                v.x = c[i][j][half * 2 + 0];
                v.y = c[i][j][half * 2 + 1];
                if (acc) {
                    float2 o = *(float2*)(crow + col);
                    v.x += o.x; v.y += o.y;
                }
                *(float2*)(crow + col) = v;
            }
        }
    }
}

// ---------------- RMSNorm ----------------
__global__ __launch_bounds__(256) void rmsnorm_kernel(
    const float* __restrict__ X, const float* __restrict__ W, float* __restrict__ O)
{
    int row = blockIdx.x;
    int t = threadIdx.x;
    const float4* x = (const float4*)(X + (long long)row * DD);
    float4 xv = x[t];
    float ss = xv.x*xv.x + xv.y*xv.y + xv.z*xv.z + xv.w*xv.w;
    #pragma unroll
    for (int off = 16; off >= 1; off >>= 1)
        ss += __shfl_xor_sync(0xffffffffu, ss, off);
    __shared__ float red[8];
    if ((t & 31) == 0) red[t >> 5] = ss;
    __syncthreads();
    __shared__ float s_inv;
    if (t == 0) {
        float tot = 0.f;
        #pragma unroll
        for (int i = 0; i < 8; i++) tot += red[i];
        s_inv = rsqrtf(tot * (1.0f / DD) + 1e-5f);
    }
    __syncthreads();
    float inv = s_inv;
    float4 wv = ((const float4*)W)[t];
    float4 ov = {xv.x*inv*wv.x, xv.y*inv*wv.y, xv.z*inv*wv.z, xv.w*inv*wv.w};
    ((float4*)(O + (long long)row * DD))[t] = ov;
}

// ---------------- SwiGLU ----------------
__global__ void silu_mul_kernel(float* __restrict__ h1, const float* __restrict__ h3, int n4)
{
    int i = blockIdx.x * blockDim.x + threadIdx.x;
    if (i >= n4) return;
    float4 a = ((float4*)h1)[i];
    float4 b = ((const float4*)h3)[i];
    a.x = a.x / (1.f + expf(-a.x)) * b.x;
    a.y = a.y / (1.f + expf(-a.y)) * b.y;
    a.z = a.z / (1.f + expf(-a.z)) * b.z;
    a.w = a.w / (1.f + expf(-a.w)) * b.w;
    ((float4*)h1)[i] = a;
}

// ---------------- RoPE ----------------
__global__ void rope_kernel(float* __restrict__ T, const float* __restrict__ fcos,
                            const float* __restrict__ fsin, int l_begin, int l_count)
{
    int idx = blockIdx.x * blockDim.x + threadIdx.x;
    int total = BB * l_count * HH * (HDIM / 2);
    if (idx >= total) return;
    int i = idx & 31;
    int h = (idx >> 5) & 15;
    int rest = idx >> 9;
    int lr = rest % l_count;
    int b = rest / l_count;
    int l = l_begin + lr;
    float* p = T + ((long long)b * LL + l) * DD + h * HDIM + 2 * i;
    float c = fcos[l * 32 + i];
    float s = fsin[l * 32 + i];
    float2 v = *(float2*)p;
    float2 o = {v.x * c - v.y * s, v.x * s + v.y * c};
    *(float2*)p = o;
}

// ---------------- Flash attention, tensor-core (mma.sync + ldmatrix) ----------------
#define AKH 0
#define AKL 9216
#define AVH 18432
#define AVL 27648

__global__ __launch_bounds__(128) void attn_mma(
    const float* __restrict__ Qg, const float* __restrict__ Kg, const float* __restrict__ Vg,
    float* __restrict__ Yg, int step)
{
    __shared__ __align__(16) unsigned char sm[36864];
    uint32_t sb = smem_u32(sm);

    int qt = blockIdx.x, h = blockIdx.y, b = blockIdx.z;
    int tid = threadIdx.x;
    int w = tid >> 5, lane = tid & 31;
    int g = lane >> 2, q = lane & 3;
    int m0 = w << 4;
    int rowin = lane & 7, l8 = (lane >> 3) & 1, l16 = (lane >> 4) & 1;

    int r  = tid >> 1;
    int ch = (tid & 1) << 5;

    unsigned koff[4], voff[4];
    #pragma unroll
    for (int jp = 0; jp < 4; jp++) {
        koff[jp] = (unsigned)((jp * 16 + l16 * 8 + rowin) * 144 + l8 * 16);
        voff[jp] = (unsigned)((l8 * 8 + rowin) * 144 + (jp * 16 + l16 * 8) * 2);
    }

    {
        const float* src = Qg + ((long long)b * LL + MM + qt * 64 + r) * DD + h * HDIM + ch;
        #pragma unroll
        for (int i = 0; i < 8; i++) {
            float4 v = *(const float4*)(src + i * 4);
            v.x *= 0.125f; v.y *= 0.125f; v.z *= 0.125f; v.w *= 0.125f;
            uint2 hv, lv;
            splitpack(v.x, v.y, hv.x, lv.x);
            splitpack(v.z, v.w, hv.y, lv.y);
            unsigned off = (unsigned)(r * 144 + (ch + i * 4) * 2);
            *(uint2*)(sm + AKH + off) = hv;
            *(uint2*)(sm + AKL + off) = lv;
        }
    }
    __syncthreads();
    uint32_t qh[4][4], ql[4][4];
    #pragma unroll
    for (int ks = 0; ks < 4; ks++) {
        int kb = ks * 32 + q * 4;
        int r0 = (m0 + g) * 144 + kb, r1 = r0 + 8 * 144;
        qh[ks][0] = *(const uint32_t*)(sm + AKH + r0);
        qh[ks][1] = *(const uint32_t*)(sm + AKH + r1);
        qh[ks][2] = *(const uint32_t*)(sm + AKH + r0 + 16);
        qh[ks][3] = *(const uint32_t*)(sm + AKH + r1 + 16);
        ql[ks][0] = *(const uint32_t*)(sm + AKL + r0);
        ql[ks][1] = *(const uint32_t*)(sm + AKL + r1);
        ql[ks][2] = *(const uint32_t*)(sm + AKL + r0 + 16);
        ql[ks][3] = *(const uint32_t*)(sm + AKL + r1 + 16);
    }

    float m_i[2] = {-1e30f, -1e30f}, l_i[2] = {0.f, 0.f};
    float o[8][4];
    #pragma unroll
    for (int j = 0; j < 8; j++)
        #pragma unroll
        for (int e = 0; e < 4; e++) o[j][e] = 0.f;

    int nkt = 9 + qt;
    for (int kt = 0; kt < nkt; kt++) {
        __syncthreads();

        const float* ksrc = Kg + ((long long)b * LL + kt * 64 + r) * DD + h * HDIM + ch;
        const float* vsrc = Vg + ((long long)b * LL + kt * 64 + r) * DD + h * HDIM + ch;
        #pragma unroll
        for (int i = 0; i < 8; i++) {
            unsigned off = (unsigned)(r * 144 + (ch + i * 4) * 2);
            float4 kv = *(const float4*)(ksrc + i * 4);
            uint2 hv, lv;
            splitpack(kv.x, kv.y, hv.x, lv.x);
            splitpack(kv.z, kv.w, hv.y, lv.y);
            *(uint2*)(sm + AKH + off) = hv;
            *(uint2*)(sm + AKL + off) = lv;

            float4 vv = *(const float4*)(vsrc + i * 4);
            splitpack(vv.x, vv.y, hv.x, lv.x);
            splitpack(vv.z, vv.w, hv.y, lv.y);
            *(uint2*)(sm + AVH + off) = hv;
            *(uint2*)(sm + AVL + off) = lv;
        }
        __syncthreads();

        float s[8][4];
        #pragma unroll
        for (int j = 0; j < 8; j++)
            #pragma unroll
            for (int e = 0; e < 4; e++) s[j][e] = 0.f;

        #pragma unroll
        for (int ks = 0; ks < 4; ks++) {
            #pragma unroll
            for (int jp = 0; jp < 4; jp++) {
                uint32_t bh[4], bl[4];
                ldsm4(bh, sb + AKH + koff[jp] + ks * 32);
                ldsm4(bl, sb + AKL + koff[jp] + ks * 32);
                mma16816(s[jp*2],   qh[ks], &bh[0]);
                mma16816(s[jp*2],   qh[ks], &bl[0]);
                mma16816(s[jp*2],   ql[ks], &bh[0]);
                mma16816(s[jp*2+1], qh[ks], &bh[2]);
                mma16816(s[jp*2+1], qh[ks], &bl[2]);
                mma16816(s[jp*2+1], ql[ks], &bh[2]);
            }
        }

        if (kt == nkt - 1) {
            #pragma unroll
            for (int j = 0; j < 8; j++)
                #pragma unroll
                for (int e = 0; e < 4; e++) {
                    int col = j * 8 + 2 * q + (e & 1);
                    int row = m0 + g + ((e >> 1) << 3);
                    if (col > row) s[j][e] = -1e30f;
                }
        }

        float mx0 = -1e30f, mx1 = -1e30f;
        #pragma unroll
        for (int j = 0; j < 8; j++) {
            mx0 = fmaxf(mx0, fmaxf(s[j][0], s[j][1]));
            mx1 = fmaxf(mx1, fmaxf(s[j][2], s[j][3]));
        }
        mx0 = fmaxf(mx0, __shfl_xor_sync(0xffffffffu, mx0, 1));
        mx0 = fmaxf(mx0, __shfl_xor_sync(0xffffffffu, mx0, 2));
        mx1 = fmaxf(mx1, __shfl_xor_sync(0xffffffffu, mx1, 1));
        mx1 = fmaxf(mx1, __shfl_xor_sync(0xffffffffu, mx1, 2));
        float mn0 = fmaxf(m_i[0], mx0), mn1 = fmaxf(m_i[1], mx1);
        float al0 = expf(m_i[0] - mn0), al1 = expf(m_i[1] - mn1);
        float sum0 = 0.f, sum1 = 0.f;
        #pragma unroll
        for (int j = 0; j < 8; j++) {
            s[j][0] = expf(s[j][0] - mn0);
            s[j][1] = expf(s[j][1] - mn0);
            s[j][2] = expf(s[j][2] - mn1);
            s[j][3] = expf(s[j][3] - mn1);
            sum0 += s[j][0] + s[j][1];
            sum1 += s[j][2] + s[j][3];
        }
        sum0 += __shfl_xor_sync(0xffffffffu, sum0, 1);
        sum0 += __shfl_xor_sync(0xffffffffu, sum0, 2);
        sum1 += __shfl_xor_sync(0xffffffffu, sum1, 1);
        sum1 += __shfl_xor_sync(0xffffffffu, sum1, 2);
        l_i[0] = l_i[0] * al0 + sum0;  m_i[0] = mn0;
        l_i[1] = l_i[1] * al1 + sum1;  m_i[1] = mn1;
        #pragma unroll
        for (int j = 0; j < 8; j++) {
            o[j][0] *= al0; o[j][1] *= al0;
            o[j][2] *= al1; o[j][3] *= al1;
        }

        #pragma unroll
        for (int ks = 0; ks < 4; ks++) {
            uint32_t pah[4], pal[4];
            splitpack(s[2*ks][0],   s[2*ks][1],   pah[0], pal[0]);
            splitpack(s[2*ks][2],   s[2*ks][3],   pah[1], pal[1]);
            splitpack(s[2*ks+1][0], s[2*ks+1][1], pah[2], pal[2]);
            splitpack(s[2*ks+1][2], s[2*ks+1][3], pah[3], pal[3]);
            #pragma unroll
            for (int jp = 0; jp < 4; jp++) {
                uint32_t vh[4], vl[4];
                ldsm4t(vh, sb + AVH + voff[jp] + ks * 2304);
                ldsm4t(vl, sb + AVL + voff[jp] + ks * 2304);
                mma16816(o[jp*2],   pah, &vh[0]);
                mma16816(o[jp*2],   pah, &vl[0]);
                mma16816(o[jp*2],   pal, &vh[0]);
                mma16816(o[jp*2+1], pah, &vh[2]);
                mma16816(o[jp*2+1], pah, &vl[2]);
                mma16816(o[jp*2+1], pal, &vh[2]);
            }
        }
    }

    float inv0 = 1.f / l_i[0], inv1 = 1.f / l_i[1];
    float* ybase = Yg + ((long long)b * SS + step * MM + qt * 64) * DD + h * HDIM;
    #pragma unroll
    for (int j = 0; j < 8; j++) {
        int col = j * 8 + 2 * q;
        float2 v0 = {o[j][0] * inv0, o[j][1] * inv0};
        float2 v1 = {o[j][2] * inv1, o[j][3] * inv1};
        *(float2*)(ybase + (long long)(m0 + g) * DD + col)     = v0;
        *(float2*)(ybase + (long long)(m0 + g + 8) * DD + col) = v1;
    }
}

// ---------------- host orchestration ----------------
static void launch_tc(const float* A,
                      const __nv_bfloat16* h0, const __nv_bfloat16* l0,
                      const __nv_bfloat16* h1, const __nv_bfloat16* l1,
                      const __nv_bfloat16* h2, const __nv_bfloat16* l2,
                      float* C0, float* C1, float* C2,
                      int nsub, int Mtot, int Nper, int K,
                      long long a_bs, int a_off, int Mchunk,
                      long long c_bs, int c_off, int acc)
{
    int nbper = Nper / 128;
    dim3 grid(nsub * nbper, Mtot / 128);
    mma_gemm<<<grid, 256, 2 * GBUF>>>(A, h0, l0, h1, l1, h2, l2, C0, C1, C2,
                                      Nper, K, nbper, a_bs, a_off, Mchunk, c_bs, c_off, acc);
}

extern "C" void kernel_launch(void* const* d_in, const int* in_sizes, int n_in,
                              void* d_out, int out_size)
{
    const float* x     = (const float*)d_in[0];
    const float* fcos  = (const float*)d_in[1];
    const float* fsin  = (const float*)d_in[2];
    const float* wq    = (const float*)d_in[3];
    const float* wk    = (const float*)d_in[4];
    const float* wv    = (const float*)d_in[5];
    const float* wo    = (const float*)d_in[6];
    const float* wm    = (const float*)d_in[7];
    const float* wkm   = (const float*)d_in[8];
    const float* wvm   = (const float*)d_in[9];
    const float* w1    = (const float*)d_in[10];
    const float* w3    = (const float*)d_in[11];
    const float* w2    = (const float*)d_in[12];
    const float* ffn_w = (const float*)d_in[13];
    const float* mem_w = (const float*)d_in[14];
    const float* omem  = (const float*)d_in[15];
    float* out = (float*)d_out;

    cudaFuncSetAttribute(mma_gemm, cudaFuncAttributeMaxDynamicSharedMemorySize, 2 * GBUF);

    float *Y, *Qb, *Kb, *Vb, *OM2, *HN, *H1, *H3, *OMN;
    __nv_bfloat16 *PH, *PL;
    cudaGetSymbolAddress((void**)&Y,   g_Y);
    cudaGetSymbolAddress((void**)&Qb,  g_Q);
    cudaGetSymbolAddress((void**)&Kb,  g_K);
    cudaGetSymbolAddress((void**)&Vb,  g_V);
    cudaGetSymbolAddress((void**)&OM2, g_OM2);
    cudaGetSymbolAddress((void**)&HN,  g_HN);
    cudaGetSymbolAddress((void**)&H1,  g_H1);
    cudaGetSymbolAddress((void**)&H3,  g_H3);
    cudaGetSymbolAddress((void**)&OMN, g_OMN);
    cudaGetSymbolAddress((void**)&PH,  g_pk_hi);
    cudaGetSymbolAddress((void**)&PL,  g_pk_lo);

    repack_sq7<<<dim3(32, 16, 7), 256>>>(wq, wk, wv, wm, wkm, wvm, wo, PH, PL);
    repack_w13<<<dim3(32, 44, 2), 256>>>(w1, w3, PH, PL);
    repack_one<<<dim3(88, 16), 256>>>(w2, PH + OFF_W2, PL + OFF_W2, DD);

    const long long XBS = (long long)SS * DD;
    const long long LBS = (long long)LL * DD;
    const long long MBS = (long long)MM * DD;

    for (int step = 0; step < NSTEP; step++) {
        launch_tc(x, PH+OFF_WQ, PL+OFF_WQ, PH+OFF_WK, PL+OFF_WK, PH+OFF_WV, PL+OFF_WV,
                  Qb, Kb, Vb, 3, BB*MM, DD, DD, XBS, step*MM, MM, LBS, MM, 0);

        if (step == 0)
            launch_tc(omem, PH+OFF_WM, PL+OFF_WM, 0,0, 0,0, OM2, 0, 0, 1,
                      BB*MM, DD, DD, 0, 0, MM, MBS, 0, 0);
        else
            launch_tc(Y, PH+OFF_WM, PL+OFF_WM, 0,0, 0,0, OM2, 0, 0, 1,
                      BB*MM, DD, DD, XBS, (step-1)*MM, MM, MBS, 0, 0);

        rmsnorm_kernel<<<BB*MM, 256>>>(OM2, ffn_w, HN);
        launch_tc(HN, PH+OFF_W1, PL+OFF_W1, PH+OFF_W3, PL+OFF_W3, 0,0,
                  H1, H3, 0, 2, BB*MM, HID, DD, 0, 0, BB*MM, 0, 0, 0);
        {
            int n4 = BB * MM * HID / 4;
            silu_mul_kernel<<<(n4 + 255) / 256, 256>>>(H1, H3, n4);
        }
        launch_tc(H1, PH+OFF_W2, PL+OFF_W2, 0,0, 0,0, OM2, 0, 0, 1,
                  BB*MM, DD, HID, 0, 0, BB*MM, 0, 0, 1);

        rmsnorm_kernel<<<BB*MM, 256>>>(OM2, mem_w, OMN);

        launch_tc(OMN, PH+OFF_WKM, PL+OFF_WKM, PH+OFF_WVM, PL+OFF_WVM, 0,0,
                  Kb, Vb, 0, 2, BB*MM, DD, DD, MBS, 0, MM, LBS, 0, 0);

        {
            int totK = BB * LL * HH * 32;
            rope_kernel<<<(totK + 255) / 256, 256>>>(Kb, fcos, fsin, 0, LL);
            int totQ = BB * MM * HH * 32;
            rope_kernel<<<(totQ + 255) / 256, 256>>>(Qb, fcos, fsin, MM, MM);
        }

        attn_mma<<<dim3(8, HH, BB), 128>>>(Qb, Kb, Vb, Y, step);
    }

    launch_tc(Y, PH+OFF_WO, PL+OFF_WO, 0,0, 0,0, out, 0, 0, 1,
              BB*SS, DD, DD, 0, 0, BB*SS, 0, 0, 0);
}

// round 8
// speedup vs baseline: 1.1887x; 1.1887x over previous
#include <cuda_runtime.h>
#include <cuda_bf16.h>
#include <math.h>
#include <stdint.h>

// Problem constants
#define BB 2
#define SS 4096
#define DD 1024
#define HH 16
#define HDIM 64
#define MM 512
#define LL 1024          // 2*MM
#define HID 2816
#define NSTEP 8          // SS/MM

// ---------------- scratch (device globals; no allocation allowed) ----------------
__device__ float g_Y  [BB * SS * DD];
__device__ float g_Q  [BB * LL * DD];
__device__ float g_K  [BB * LL * DD];
__device__ float g_V  [BB * LL * DD];
__device__ float g_OM2[BB * MM * DD];
__device__ float g_HN [BB * MM * DD];
__device__ float g_H1 [BB * MM * HID];
__device__ float g_H3 [BB * MM * HID];
__device__ float g_OMN[BB * MM * DD];

// packed bf16 hi/lo weight tiles: (n_blk 64 x k_chunk 32), n-major, 80B row stride.
#define TILE_B 5120
#define PK_SQ  (512 * 2560)
#define PK_W13 (1408 * 2560)
#define PK_W2  (1408 * 2560)
#define PK_TOTAL (7*PK_SQ + 2*PK_W13 + PK_W2)
__device__ __align__(256) __nv_bfloat16 g_pk_hi[PK_TOTAL];
__device__ __align__(256) __nv_bfloat16 g_pk_lo[PK_TOTAL];

#define OFF_WQ  0
#define OFF_WK  (1*PK_SQ)
#define OFF_WV  (2*PK_SQ)
#define OFF_WM  (3*PK_SQ)
#define OFF_WKM (4*PK_SQ)
#define OFF_WVM (5*PK_SQ)
#define OFF_WO  (6*PK_SQ)
#define OFF_W1  (7*PK_SQ)
#define OFF_W3  (7*PK_SQ + PK_W13)
#define OFF_W2  (7*PK_SQ + 2*PK_W13)

// ---------------- mma / ldmatrix / cp.async helpers (baseline PTX) ----------------
__device__ __forceinline__ void mma16816(float* c, const uint32_t* a, const uint32_t* b) {
    asm volatile(
        "mma.sync.aligned.m16n8k16.row.col.f32.bf16.bf16.f32 "
        "{%0,%1,%2,%3}, {%4,%5,%6,%7}, {%8,%9}, {%0,%1,%2,%3};"
        : "+f"(c[0]), "+f"(c[1]), "+f"(c[2]), "+f"(c[3])
        : "r"(a[0]), "r"(a[1]), "r"(a[2]), "r"(a[3]), "r"(b[0]), "r"(b[1]));
}
__device__ __forceinline__ void ldsm4(uint32_t* r, uint32_t addr) {
    asm volatile("ldmatrix.sync.aligned.m8n8.x4.shared.b16 {%0,%1,%2,%3}, [%4];"
        : "=r"(r[0]), "=r"(r[1]), "=r"(r[2]), "=r"(r[3]) : "r"(addr));
}
__device__ __forceinline__ void ldsm4t(uint32_t* r, uint32_t addr) {
    asm volatile("ldmatrix.sync.aligned.m8n8.x4.trans.shared.b16 {%0,%1,%2,%3}, [%4];"
        : "=r"(r[0]), "=r"(r[1]), "=r"(r[2]), "=r"(r[3]) : "r"(addr));
}
__device__ __forceinline__ uint32_t smem_u32(const void* p) {
    uint32_t a;
    asm("{ .reg .u64 t; cvta.to.shared.u64 t, %1; cvt.u32.u64 %0, t; }" : "=r"(a) : "l"(p));
    return a;
}
__device__ __forceinline__ void cpasync16(uint32_t saddr, const void* gptr) {
    asm volatile("cp.async.ca.shared.global [%0], [%1], 16;" :: "r"(saddr), "l"(gptr));
}
#define CP_COMMIT() asm volatile("cp.async.commit_group;" ::: "memory")
#define CP_WAIT0()  asm volatile("cp.async.wait_group 0;" ::: "memory")

__device__ __forceinline__ void splitpack(float x, float y, uint32_t& hi, uint32_t& lo) {
    __nv_bfloat16 hx = __float2bfloat16_rn(x);
    __nv_bfloat16 hy = __float2bfloat16_rn(y);
    __nv_bfloat16 lx = __float2bfloat16_rn(x - __bfloat162float(hx));
    __nv_bfloat16 ly = __float2bfloat16_rn(y - __bfloat162float(hy));
    hi = (uint32_t)__bfloat16_as_ushort(hx) | ((uint32_t)__bfloat16_as_ushort(hy) << 16);
    lo = (uint32_t)__bfloat16_as_ushort(lx) | ((uint32_t)__bfloat16_as_ushort(ly) << 16);
}

// ================= weight repack: fp32 [K,N] -> n-major bf16 hi/lo tiles =================
__device__ __forceinline__ void repack_body(
    const float* __restrict__ W, __nv_bfloat16* __restrict__ Wh,
    __nv_bfloat16* __restrict__ Wl, int N, int KC, int kc, int nb)
{
    __shared__ unsigned char sh[TILE_B];
    __shared__ unsigned char sl[TILE_B];
    for (int e = threadIdx.x; e < 2048; e += 256) {
        int n_l = e & 63, k_l = e >> 6;
        float v = W[(long long)(kc * 32 + k_l) * N + nb * 64 + n_l];
        __nv_bfloat16 h = __float2bfloat16_rn(v);
        __nv_bfloat16 l = __float2bfloat16_rn(v - __bfloat162float(h));
        unsigned off = (unsigned)(n_l * 80 + k_l * 2);
        *(__nv_bfloat16*)(sh + off) = h;
        *(__nv_bfloat16*)(sl + off) = l;
    }
    __syncthreads();
    long long tb = ((long long)nb * KC + kc) * TILE_B;
    uint4* dh = (uint4*)((char*)Wh + tb);
    uint4* dl = (uint4*)((char*)Wl + tb);
    int t = threadIdx.x;
    dh[t] = ((uint4*)sh)[t];
    dl[t] = ((uint4*)sl)[t];
    if (t < 64) {
        dh[256 + t] = ((uint4*)sh)[256 + t];
        dl[256 + t] = ((uint4*)sl)[256 + t];
    }
}

__global__ __launch_bounds__(256) void repack_sq7(
    const float* w0, const float* w1, const float* w2, const float* w3,
    const float* w4, const float* w5, const float* w6,
    __nv_bfloat16* PH, __nv_bfloat16* PL)
{
    int z = blockIdx.z;
    const float* W = (z == 0) ? w0 : (z == 1) ? w1 : (z == 2) ? w2 :
                     (z == 3) ? w3 : (z == 4) ? w4 : (z == 5) ? w5 : w6;
    repack_body(W, PH + (long long)z * PK_SQ, PL + (long long)z * PK_SQ,
                DD, 32, blockIdx.x, blockIdx.y);
}
__global__ __launch_bounds__(256) void repack_w13(
    const float* w1, const float* w3, __nv_bfloat16* PH, __nv_bfloat16* PL)
{
    int z = blockIdx.z;
    repack_body(z ? w3 : w1, PH + OFF_W1 + (long long)z * PK_W13,
                PL + OFF_W1 + (long long)z * PK_W13, HID, 32, blockIdx.x, blockIdx.y);
}
__global__ __launch_bounds__(256) void repack_one(
    const float* W, __nv_bfloat16* Wh, __nv_bfloat16* Wl, int N)
{
    repack_body(W, Wh, Wl, N, gridDim.x, blockIdx.x, blockIdx.y);
}

// ================= mma.sync GEMM: CTA 128x64, 4 warps (warp 32x64), cp.async B =================
// C[row,col] (+)= A[row,:] @ B, bf16 hi/lo split (AhBh + AhBl + AlBh, fp32 acc).
// BK=32, 128 threads. Double-buffered smem (R6 layout). Requires 128 | Mchunk.
#define SA_H 0
#define SA_L 10240
#define SB_H 20480
#define SB_L 25600
#define GBUF 30720

__global__ __launch_bounds__(128, 3) void mma_gemm(
    const float* __restrict__ A,
    const __nv_bfloat16* __restrict__ Bh0, const __nv_bfloat16* __restrict__ Bl0,
    const __nv_bfloat16* __restrict__ Bh1, const __nv_bfloat16* __restrict__ Bl1,
    const __nv_bfloat16* __restrict__ Bh2, const __nv_bfloat16* __restrict__ Bl2,
    float* __restrict__ C0, float* __restrict__ C1, float* __restrict__ C2,
    int Nper, int K, int nbper,
    long long a_bs, int a_off, int Mchunk,
    long long c_bs, int c_off, int acc)
{
    extern __shared__ __align__(16) unsigned char smem[];
    uint32_t sb = smem_u32(smem);

    int tid = threadIdx.x;
    int w = tid >> 5, lane = tid & 31;
    int g = lane >> 2, q = lane & 3;
    int rowin = lane & 7, l8 = (lane >> 3) & 1, l16 = (lane >> 4) & 1;

    int sel = blockIdx.x / nbper;
    int n_blk = blockIdx.x - sel * nbper;
    int block_n = n_blk * 64;
    int block_m = blockIdx.y * 128;
    const __nv_bfloat16* Bh = (sel == 0) ? Bh0 : ((sel == 1) ? Bh1 : Bh2);
    const __nv_bfloat16* Bl = (sel == 0) ? Bl0 : ((sel == 1) ? Bl1 : Bl2);
    float*               C  = (sel == 0) ? C0  : ((sel == 1) ? C1  : C2);

    int nk = K >> 5;

    // A base: the 128-row block never crosses an Mchunk boundary (128 | Mchunk)
    const float* abase = A + (long long)(block_m / Mchunk) * a_bs
                       + (long long)((block_m % Mchunk) + a_off) * K;
    int r0 = tid >> 3, c4 = tid & 7;              // 8 rows spaced 16 apart per thread
    unsigned ast0 = (unsigned)(r0 * 80 + c4 * 8);

    const char* bh_src = (const char*)Bh + (long long)n_blk * nk * TILE_B;
    const char* bl_src = (const char*)Bl + (long long)n_blk * nk * TILE_B;

    // ldmatrix fragment offsets (R6-verified layout)
    unsigned a_frag_off[2];
    #pragma unroll
    for (int i = 0; i < 2; i++)
        a_frag_off[i] = (unsigned)((w * 32 + i * 16 + rowin + l8 * 8) * 80 + l16 * 16);
    unsigned b_frag_off[4];
    #pragma unroll
    for (int jp = 0; jp < 4; jp++)
        b_frag_off[jp] = (unsigned)((jp * 16 + rowin + l16 * 8) * 80 + l8 * 16);

    float c[2][8][4];
    #pragma unroll
    for (int i = 0; i < 2; i++)
        #pragma unroll
        for (int j = 0; j < 8; j++)
            #pragma unroll
            for (int e = 0; e < 4; e++) c[i][j][e] = 0.f;

    // ---- B copy via cp.async (5120B per hi/lo tile; 320 uint4) ----
    #define ISSUE_B(bufbase, chunk) do {                                          \
        long long _bo = (long long)(chunk) * TILE_B;                              \
        uint32_t _dh = sb + (bufbase) + SB_H;                                     \
        uint32_t _dl = sb + (bufbase) + SB_L;                                     \
        const char* _sh = bh_src + _bo;                                           \
        const char* _sl = bl_src + _bo;                                           \
        cpasync16(_dh + tid * 16, _sh + tid * 16);                                \
        cpasync16(_dh + (128 + tid) * 16, _sh + (128 + tid) * 16);                \
        cpasync16(_dl + tid * 16, _sl + tid * 16);                                \
        cpasync16(_dl + (128 + tid) * 16, _sl + (128 + tid) * 16);                \
        if (tid < 64) {                                                           \
            cpasync16(_dh + (256 + tid) * 16, _sh + (256 + tid) * 16);            \
            cpasync16(_dl + (256 + tid) * 16, _sl + (256 + tid) * 16);            \
        }                                                                         \
        CP_COMMIT();                                                              \
    } while (0)

    float4 pa[8];
    // ---- chunk 0 ----
    ISSUE_B(0, 0);
    #pragma unroll
    for (int j = 0; j < 8; j++)
        pa[j] = *(const float4*)(abase + (long long)(r0 + 16 * j) * K + c4 * 4);
    #pragma unroll
    for (int j = 0; j < 8; j++) {
        float4 v = pa[j];
        uint2 hv, lv;
        splitpack(v.x, v.y, hv.x, lv.x);
        splitpack(v.z, v.w, hv.y, lv.y);
        *(uint2*)(smem + SA_H + ast0 + j * (16 * 80)) = hv;
        *(uint2*)(smem + SA_L + ast0 + j * (16 * 80)) = lv;
    }
    CP_WAIT0();
    __syncthreads();

    int cur = 0;
    for (int it = 0; it < nk; it++) {
        bool hn = (it + 1 < nk);
        uint32_t nxtbase = (cur ^ 1) * GBUF;
        if (hn) {
            ISSUE_B(nxtbase, it + 1);
            #pragma unroll
            for (int j = 0; j < 8; j++)
                pa[j] = *(const float4*)(abase + (long long)(r0 + 16 * j) * K
                                         + (it + 1) * 32 + c4 * 4);
        }

        // compute from buffer cur
        uint32_t abh = sb + cur * GBUF + SA_H;
        uint32_t abl = sb + cur * GBUF + SA_L;
        uint32_t bbh = sb + cur * GBUF + SB_H;
        uint32_t bbl = sb + cur * GBUF + SB_L;
        #pragma unroll
        for (int kk = 0; kk < 2; kk++) {
            int kb = kk * 32;
            uint32_t ah[2][4], al[2][4];
            #pragma unroll
            for (int i = 0; i < 2; i++) {
                ldsm4(ah[i], abh + a_frag_off[i] + kb);
                ldsm4(al[i], abl + a_frag_off[i] + kb);
            }
            #pragma unroll
            for (int jp = 0; jp < 4; jp++) {
                uint32_t bh[4], bl[4];
                ldsm4(bh, bbh + b_frag_off[jp] + kb);
                ldsm4(bl, bbl + b_frag_off[jp] + kb);
                #pragma unroll
                for (int i = 0; i < 2; i++) {
                    mma16816(c[i][jp*2],   ah[i], &bh[0]);
                    mma16816(c[i][jp*2],   ah[i], &bl[0]);
                    mma16816(c[i][jp*2],   al[i], &bh[0]);
                    mma16816(c[i][jp*2+1], ah[i], &bh[2]);
                    mma16816(c[i][jp*2+1], ah[i], &bl[2]);
                    mma16816(c[i][jp*2+1], al[i], &bh[2]);
                }
            }
        }

        if (hn) {
            #pragma unroll
            for (int j = 0; j < 8; j++) {
                float4 v = pa[j];
                uint2 hv, lv;
                splitpack(v.x, v.y, hv.x, lv.x);
                splitpack(v.z, v.w, hv.y, lv.y);
                *(uint2*)(smem + nxtbase + SA_H + ast0 + j * (16 * 80)) = hv;
                *(uint2*)(smem + nxtbase + SA_L + ast0 + j * (16 * 80)) = lv;
            }
            CP_WAIT0();
            __syncthreads();
            cur ^= 1;
        }
    }
    #undef ISSUE_B

    // epilogue: block rows never cross an Mchunk boundary
    float* cbase = C + (long long)(block_m / Mchunk) * c_bs
                 + (long long)((block_m % Mchunk) + c_off) * Nper + block_n;
    #pragma unroll
    for (int i = 0; i < 2; i++) {
        #pragma unroll
        for (int half = 0; half < 2; half++) {
            int lrow = w * 32 + i * 16 + g + half * 8;
            float* crow = cbase + (long long)lrow * Nper;
            #pragma unroll
            for (int j = 0; j < 8; j++) {
                int col = j * 8 + 2 * q;
                float2 v;
                v.x = c[i][j][half * 2 + 0];
                v.y = c[i][j][half * 2 + 1];
                if (acc) {
                    float2 o = *(float2*)(crow + col);
                    v.x += o.x; v.y += o.y;
                }
                *(float2*)(crow + col) = v;
            }
        }
    }
}

// ---------------- RMSNorm ----------------
__global__ __launch_bounds__(256) void rmsnorm_kernel(
    const float* __restrict__ X, const float* __restrict__ W, float* __restrict__ O)
{
    int row = blockIdx.x;
    int t = threadIdx.x;
    const float4* x = (const float4*)(X + (long long)row * DD);
    float4 xv = x[t];
    float ss = xv.x*xv.x + xv.y*xv.y + xv.z*xv.z + xv.w*xv.w;
    #pragma unroll
    for (int off = 16; off >= 1; off >>= 1)
        ss += __shfl_xor_sync(0xffffffffu, ss, off);
    __shared__ float red[8];
    if ((t & 31) == 0) red[t >> 5] = ss;
    __syncthreads();
    __shared__ float s_inv;
    if (t == 0) {
        float tot = 0.f;
        #pragma unroll
        for (int i = 0; i < 8; i++) tot += red[i];
        s_inv = rsqrtf(tot * (1.0f / DD) + 1e-5f);
    }
    __syncthreads();
    float inv = s_inv;
    float4 wv = ((const float4*)W)[t];
    float4 ov = {xv.x*inv*wv.x, xv.y*inv*wv.y, xv.z*inv*wv.z, xv.w*inv*wv.w};
    ((float4*)(O + (long long)row * DD))[t] = ov;
}

// ---------------- SwiGLU ----------------
__global__ void silu_mul_kernel(float* __restrict__ h1, const float* __restrict__ h3, int n4)
{
    int i = blockIdx.x * blockDim.x + threadIdx.x;
    if (i >= n4) return;
    float4 a = ((float4*)h1)[i];
    float4 b = ((const float4*)h3)[i];
    a.x = a.x / (1.f + expf(-a.x)) * b.x;
    a.y = a.y / (1.f + expf(-a.y)) * b.y;
    a.z = a.z / (1.f + expf(-a.z)) * b.z;
    a.w = a.w / (1.f + expf(-a.w)) * b.w;
    ((float4*)h1)[i] = a;
}

// ---------------- RoPE ----------------
__global__ void rope_kernel(float* __restrict__ T, const float* __restrict__ fcos,
                            const float* __restrict__ fsin, int l_begin, int l_count)
{
    int idx = blockIdx.x * blockDim.x + threadIdx.x;
    int total = BB * l_count * HH * (HDIM / 2);
    if (idx >= total) return;
    int i = idx & 31;
    int h = (idx >> 5) & 15;
    int rest = idx >> 9;
    int lr = rest % l_count;
    int b = rest / l_count;
    int l = l_begin + lr;
    float* p = T + ((long long)b * LL + l) * DD + h * HDIM + 2 * i;
    float c = fcos[l * 32 + i];
    float s = fsin[l * 32 + i];
    float2 v = *(float2*)p;
    float2 o = {v.x * c - v.y * s, v.x * s + v.y * c};
    *(float2*)p = o;
}

// ---------------- Flash attention (unchanged from R6 — verified) ----------------
#define AKH 0
#define AKL 9216
#define AVH 18432
#define AVL 27648

__global__ __launch_bounds__(128) void attn_mma(
    const float* __restrict__ Qg, const float* __restrict__ Kg, const float* __restrict__ Vg,
    float* __restrict__ Yg, int step)
{
    __shared__ __align__(16) unsigned char sm[36864];
    uint32_t sb = smem_u32(sm);

    int qt = blockIdx.x, h = blockIdx.y, b = blockIdx.z;
    int tid = threadIdx.x;
    int w = tid >> 5, lane = tid & 31;
    int g = lane >> 2, q = lane & 3;
    int m0 = w << 4;
    int rowin = lane & 7, l8 = (lane >> 3) & 1, l16 = (lane >> 4) & 1;

    int r  = tid >> 1;
    int ch = (tid & 1) << 5;

    unsigned koff[4], voff[4];
    #pragma unroll
    for (int jp = 0; jp < 4; jp++) {
        koff[jp] = (unsigned)((jp * 16 + l16 * 8 + rowin) * 144 + l8 * 16);
        voff[jp] = (unsigned)((l8 * 8 + rowin) * 144 + (jp * 16 + l16 * 8) * 2);
    }

    {
        const float* src = Qg + ((long long)b * LL + MM + qt * 64 + r) * DD + h * HDIM + ch;
        #pragma unroll
        for (int i = 0; i < 8; i++) {
            float4 v = *(const float4*)(src + i * 4);
            v.x *= 0.125f; v.y *= 0.125f; v.z *= 0.125f; v.w *= 0.125f;
            uint2 hv, lv;
            splitpack(v.x, v.y, hv.x, lv.x);
            splitpack(v.z, v.w, hv.y, lv.y);
            unsigned off = (unsigned)(r * 144 + (ch + i * 4) * 2);
            *(uint2*)(sm + AKH + off) = hv;
            *(uint2*)(sm + AKL + off) = lv;
        }
    }
    __syncthreads();
    uint32_t qh[4][4], ql[4][4];
    #pragma unroll
    for (int ks = 0; ks < 4; ks++) {
        int kb = ks * 32 + q * 4;
        int r0 = (m0 + g) * 144 + kb, r1 = r0 + 8 * 144;
        qh[ks][0] = *(const uint32_t*)(sm + AKH + r0);
        qh[ks][1] = *(const uint32_t*)(sm + AKH + r1);
        qh[ks][2] = *(const uint32_t*)(sm + AKH + r0 + 16);
        qh[ks][3] = *(const uint32_t*)(sm + AKH + r1 + 16);
        ql[ks][0] = *(const uint32_t*)(sm + AKL + r0);
        ql[ks][1] = *(const uint32_t*)(sm + AKL + r1);
        ql[ks][2] = *(const uint32_t*)(sm + AKL + r0 + 16);
        ql[ks][3] = *(const uint32_t*)(sm + AKL + r1 + 16);
    }

    float m_i[2] = {-1e30f, -1e30f}, l_i[2] = {0.f, 0.f};
    float o[8][4];
    #pragma unroll
    for (int j = 0; j < 8; j++)
        #pragma unroll
        for (int e = 0; e < 4; e++) o[j][e] = 0.f;

    int nkt = 9 + qt;
    for (int kt = 0; kt < nkt; kt++) {
        __syncthreads();

        const float* ksrc = Kg + ((long long)b * LL + kt * 64 + r) * DD + h * HDIM + ch;
        const float* vsrc = Vg + ((long long)b * LL + kt * 64 + r) * DD + h * HDIM + ch;
        #pragma unroll
        for (int i = 0; i < 8; i++) {
            unsigned off = (unsigned)(r * 144 + (ch + i * 4) * 2);
            float4 kv = *(const float4*)(ksrc + i * 4);
            uint2 hv, lv;
            splitpack(kv.x, kv.y, hv.x, lv.x);
            splitpack(kv.z, kv.w, hv.y, lv.y);
            *(uint2*)(sm + AKH + off) = hv;
            *(uint2*)(sm + AKL + off) = lv;

            float4 vv = *(const float4*)(vsrc + i * 4);
            splitpack(vv.x, vv.y, hv.x, lv.x);
            splitpack(vv.z, vv.w, hv.y, lv.y);
            *(uint2*)(sm + AVH + off) = hv;
            *(uint2*)(sm + AVL + off) = lv;
        }
        __syncthreads();

        float s[8][4];
        #pragma unroll
        for (int j = 0; j < 8; j++)
            #pragma unroll
            for (int e = 0; e < 4; e++) s[j][e] = 0.f;

        #pragma unroll
        for (int ks = 0; ks < 4; ks++) {
            #pragma unroll
            for (int jp = 0; jp < 4; jp++) {
                uint32_t bh[4], bl[4];
                ldsm4(bh, sb + AKH + koff[jp] + ks * 32);
                ldsm4(bl, sb + AKL + koff[jp] + ks * 32);
                mma16816(s[jp*2],   qh[ks], &bh[0]);
                mma16816(s[jp*2],   qh[ks], &bl[0]);
                mma16816(s[jp*2],   ql[ks], &bh[0]);
                mma16816(s[jp*2+1], qh[ks], &bh[2]);
                mma16816(s[jp*2+1], qh[ks], &bl[2]);
                mma16816(s[jp*2+1], ql[ks], &bh[2]);
            }
        }

        if (kt == nkt - 1) {
            #pragma unroll
            for (int j = 0; j < 8; j++)
                #pragma unroll
                for (int e = 0; e < 4; e++) {
                    int col = j * 8 + 2 * q + (e & 1);
                    int row = m0 + g + ((e >> 1) << 3);
                    if (col > row) s[j][e] = -1e30f;
                }
        }

        float mx0 = -1e30f, mx1 = -1e30f;
        #pragma unroll
        for (int j = 0; j < 8; j++) {
            mx0 = fmaxf(mx0, fmaxf(s[j][0], s[j][1]));
            mx1 = fmaxf(mx1, fmaxf(s[j][2], s[j][3]));
        }
        mx0 = fmaxf(mx0, __shfl_xor_sync(0xffffffffu, mx0, 1));
        mx0 = fmaxf(mx0, __shfl_xor_sync(0xffffffffu, mx0, 2));
        mx1 = fmaxf(mx1, __shfl_xor_sync(0xffffffffu, mx1, 1));
        mx1 = fmaxf(mx1, __shfl_xor_sync(0xffffffffu, mx1, 2));
        float mn0 = fmaxf(m_i[0], mx0), mn1 = fmaxf(m_i[1], mx1);
        float al0 = expf(m_i[0] - mn0), al1 = expf(m_i[1] - mn1);
        float sum0 = 0.f, sum1 = 0.f;
        #pragma unroll
        for (int j = 0; j < 8; j++) {
            s[j][0] = expf(s[j][0] - mn0);
            s[j][1] = expf(s[j][1] - mn0);
            s[j][2] = expf(s[j][2] - mn1);
            s[j][3] = expf(s[j][3] - mn1);
            sum0 += s[j][0] + s[j][1];
            sum1 += s[j][2] + s[j][3];
        }
        sum0 += __shfl_xor_sync(0xffffffffu, sum0, 1);
        sum0 += __shfl_xor_sync(0xffffffffu, sum0, 2);
        sum1 += __shfl_xor_sync(0xffffffffu, sum1, 1);
        sum1 += __shfl_xor_sync(0xffffffffu, sum1, 2);
        l_i[0] = l_i[0] * al0 + sum0;  m_i[0] = mn0;
        l_i[1] = l_i[1] * al1 + sum1;  m_i[1] = mn1;
        #pragma unroll
        for (int j = 0; j < 8; j++) {
            o[j][0] *= al0; o[j][1] *= al0;
            o[j][2] *= al1; o[j][3] *= al1;
        }

        #pragma unroll
        for (int ks = 0; ks < 4; ks++) {
            uint32_t pah[4], pal[4];
            splitpack(s[2*ks][0],   s[2*ks][1],   pah[0], pal[0]);
            splitpack(s[2*ks][2],   s[2*ks][3],   pah[1], pal[1]);
            splitpack(s[2*ks+1][0], s[2*ks+1][1], pah[2], pal[2]);
            splitpack(s[2*ks+1][2], s[2*ks+1][3], pah[3], pal[3]);
            #pragma unroll
            for (int jp = 0; jp < 4; jp++) {
                uint32_t vh[4], vl[4];
                ldsm4t(vh, sb + AVH + voff[jp] + ks * 2304);
                ldsm4t(vl, sb + AVL + voff[jp] + ks * 2304);
                mma16816(o[jp*2],   pah, &vh[0]);
                mma16816(o[jp*2],   pah, &vl[0]);
                mma16816(o[jp*2],   pal, &vh[0]);
                mma16816(o[jp*2+1], pah, &vh[2]);
                mma16816(o[jp*2+1], pah, &vl[2]);
                mma16816(o[jp*2+1], pal, &vh[2]);
            }
        }
    }

    float inv0 = 1.f / l_i[0], inv1 = 1.f / l_i[1];
    float* ybase = Yg + ((long long)b * SS + step * MM + qt * 64) * DD + h * HDIM;
    #pragma unroll
    for (int j = 0; j < 8; j++) {
        int col = j * 8 + 2 * q;
        float2 v0 = {o[j][0] * inv0, o[j][1] * inv0};
        float2 v1 = {o[j][2] * inv1, o[j][3] * inv1};
        *(float2*)(ybase + (long long)(m0 + g) * DD + col)     = v0;
        *(float2*)(ybase + (long long)(m0 + g + 8) * DD + col) = v1;
    }
}

// ---------------- host orchestration ----------------
static void launch_tc(const float* A,
                      const __nv_bfloat16* h0, const __nv_bfloat16* l0,
                      const __nv_bfloat16* h1, const __nv_bfloat16* l1,
                      const __nv_bfloat16* h2, const __nv_bfloat16* l2,
                      float* C0, float* C1, float* C2,
                      int nsub, int Mtot, int Nper, int K,
                      long long a_bs, int a_off, int Mchunk,
                      long long c_bs, int c_off, int acc)
{
    int nbper = Nper / 64;
    dim3 grid(nsub * nbper, Mtot / 128);
    mma_gemm<<<grid, 128, 2 * GBUF>>>(A, h0, l0, h1, l1, h2, l2, C0, C1, C2,
                                      Nper, K, nbper, a_bs, a_off, Mchunk, c_bs, c_off, acc);
}

extern "C" void kernel_launch(void* const* d_in, const int* in_sizes, int n_in,
                              void* d_out, int out_size)
{
    const float* x     = (const float*)d_in[0];
    const float* fcos  = (const float*)d_in[1];
    const float* fsin  = (const float*)d_in[2];
    const float* wq    = (const float*)d_in[3];
    const float* wk    = (const float*)d_in[4];
    const float* wv    = (const float*)d_in[5];
    const float* wo    = (const float*)d_in[6];
    const float* wm    = (const float*)d_in[7];
    const float* wkm   = (const float*)d_in[8];
    const float* wvm   = (const float*)d_in[9];
    const float* w1    = (const float*)d_in[10];
    const float* w3    = (const float*)d_in[11];
    const float* w2    = (const float*)d_in[12];
    const float* ffn_w = (const float*)d_in[13];
    const float* mem_w = (const float*)d_in[14];
    const float* omem  = (const float*)d_in[15];
    float* out = (float*)d_out;

    cudaFuncSetAttribute(mma_gemm, cudaFuncAttributeMaxDynamicSharedMemorySize, 2 * GBUF);

    float *Y, *Qb, *Kb, *Vb, *OM2, *HN, *H1, *H3, *OMN;
    __nv_bfloat16 *PH, *PL;
    cudaGetSymbolAddress((void**)&Y,   g_Y);
    cudaGetSymbolAddress((void**)&Qb,  g_Q);
    cudaGetSymbolAddress((void**)&Kb,  g_K);
    cudaGetSymbolAddress((void**)&Vb,  g_V);
    cudaGetSymbolAddress((void**)&OM2, g_OM2);
    cudaGetSymbolAddress((void**)&HN,  g_HN);
    cudaGetSymbolAddress((void**)&H1,  g_H1);
    cudaGetSymbolAddress((void**)&H3,  g_H3);
    cudaGetSymbolAddress((void**)&OMN, g_OMN);
    cudaGetSymbolAddress((void**)&PH,  g_pk_hi);
    cudaGetSymbolAddress((void**)&PL,  g_pk_lo);

    repack_sq7<<<dim3(32, 16, 7), 256>>>(wq, wk, wv, wm, wkm, wvm, wo, PH, PL);
    repack_w13<<<dim3(32, 44, 2), 256>>>(w1, w3, PH, PL);
    repack_one<<<dim3(88, 16), 256>>>(w2, PH + OFF_W2, PL + OFF_W2, DD);

    const long long XBS = (long long)SS * DD;
    const long long LBS = (long long)LL * DD;
    const long long MBS = (long long)MM * DD;

    for (int step = 0; step < NSTEP; step++) {
        launch_tc(x, PH+OFF_WQ, PL+OFF_WQ, PH+OFF_WK, PL+OFF_WK, PH+OFF_WV, PL+OFF_WV,
                  Qb, Kb, Vb, 3, BB*MM, DD, DD, XBS, step*MM, MM, LBS, MM, 0);

        if (step == 0)
            launch_tc(omem, PH+OFF_WM, PL+OFF_WM, 0,0, 0,0, OM2, 0, 0, 1,
                      BB*MM, DD, DD, 0, 0, MM, MBS, 0, 0);
        else
            launch_tc(Y, PH+OFF_WM, PL+OFF_WM, 0,0, 0,0, OM2, 0, 0, 1,
                      BB*MM, DD, DD, XBS, (step-1)*MM, MM, MBS, 0, 0);

        rmsnorm_kernel<<<BB*MM, 256>>>(OM2, ffn_w, HN);
        launch_tc(HN, PH+OFF_W1, PL+OFF_W1, PH+OFF_W3, PL+OFF_W3, 0,0,
                  H1, H3, 0, 2, BB*MM, HID, DD, 0, 0, BB*MM, 0, 0, 0);
        {
            int n4 = BB * MM * HID / 4;
            silu_mul_kernel<<<(n4 + 255) / 256, 256>>>(H1, H3, n4);
        }
        launch_tc(H1, PH+OFF_W2, PL+OFF_W2, 0,0, 0,0, OM2, 0, 0, 1,
                  BB*MM, DD, HID, 0, 0, BB*MM, 0, 0, 1);

        rmsnorm_kernel<<<BB*MM, 256>>>(OM2, mem_w, OMN);

        launch_tc(OMN, PH+OFF_WKM, PL+OFF_WKM, PH+OFF_WVM, PL+OFF_WVM, 0,0,
                  Kb, Vb, 0, 2, BB*MM, DD, DD, MBS, 0, MM, LBS, 0, 0);

        {
            int totK = BB * LL * HH * 32;
            rope_kernel<<<(totK + 255) / 256, 256>>>(Kb, fcos, fsin, 0, LL);
            int totQ = BB * MM * HH * 32;
            rope_kernel<<<(totQ + 255) / 256, 256>>>(Qb, fcos, fsin, MM, MM);
        }

        attn_mma<<<dim3(8, HH, BB), 128>>>(Qb, Kb, Vb, Y, step);
    }

    launch_tc(Y, PH+OFF_WO, PL+OFF_WO, 0,0, 0,0, out, 0, 0, 1,
              BB*SS, DD, DD, 0, 0, BB*SS, 0, 0, 0);
}

// round 9
// speedup vs baseline: 1.2239x; 1.0296x over previous
#include <cuda_runtime.h>
#include <cuda_bf16.h>
#include <math.h>
#include <stdint.h>

// Problem constants
#define BB 2
#define SS 4096
#define DD 1024
#define HH 16
#define HDIM 64
#define MM 512
#define LL 1024          // 2*MM
#define HID 2816
#define NSTEP 8          // SS/MM

// ---------------- scratch (device globals; no allocation allowed) ----------------
__device__ float g_Y  [BB * SS * DD];   // attention outputs / om chain
__device__ float g_XQ [BB * SS * DD];   // x-side Q for all steps (RoPE'd once)
__device__ float g_XK [BB * SS * DD];
__device__ float g_XV [BB * SS * DD];
__device__ float g_MK [BB * MM * DD];   // per-step memory K (RoPE'd per step)
__device__ float g_MV [BB * MM * DD];
__device__ float g_OM2[BB * MM * DD];
__device__ float g_HN [BB * MM * DD];
__device__ float g_H1 [BB * MM * HID];
__device__ float g_H3 [BB * MM * HID];
__device__ float g_OMN[BB * MM * DD];

// packed bf16 hi/lo weight tiles: (n_blk 64 x k_chunk 32), n-major, 80B row stride.
#define TILE_B 5120
#define PK_SQ  (512 * 2560)
#define PK_W13 (1408 * 2560)
#define PK_W2  (1408 * 2560)
#define PK_TOTAL (7*PK_SQ + 2*PK_W13 + PK_W2)
__device__ __align__(256) __nv_bfloat16 g_pk_hi[PK_TOTAL];
__device__ __align__(256) __nv_bfloat16 g_pk_lo[PK_TOTAL];

#define OFF_WQ  0
#define OFF_WK  (1*PK_SQ)
#define OFF_WV  (2*PK_SQ)
#define OFF_WM  (3*PK_SQ)
#define OFF_WKM (4*PK_SQ)
#define OFF_WVM (5*PK_SQ)
#define OFF_WO  (6*PK_SQ)
#define OFF_W1  (7*PK_SQ)
#define OFF_W3  (7*PK_SQ + PK_W13)
#define OFF_W2  (7*PK_SQ + 2*PK_W13)

// ---------------- mma / ldmatrix / cp.async helpers (baseline PTX) ----------------
__device__ __forceinline__ void mma16816(float* c, const uint32_t* a, const uint32_t* b) {
    asm volatile(
        "mma.sync.aligned.m16n8k16.row.col.f32.bf16.bf16.f32 "
        "{%0,%1,%2,%3}, {%4,%5,%6,%7}, {%8,%9}, {%0,%1,%2,%3};"
        : "+f"(c[0]), "+f"(c[1]), "+f"(c[2]), "+f"(c[3])
        : "r"(a[0]), "r"(a[1]), "r"(a[2]), "r"(a[3]), "r"(b[0]), "r"(b[1]));
}
__device__ __forceinline__ void ldsm4(uint32_t* r, uint32_t addr) {
    asm volatile("ldmatrix.sync.aligned.m8n8.x4.shared.b16 {%0,%1,%2,%3}, [%4];"
        : "=r"(r[0]), "=r"(r[1]), "=r"(r[2]), "=r"(r[3]) : "r"(addr));
}
__device__ __forceinline__ void ldsm4t(uint32_t* r, uint32_t addr) {
    asm volatile("ldmatrix.sync.aligned.m8n8.x4.trans.shared.b16 {%0,%1,%2,%3}, [%4];"
        : "=r"(r[0]), "=r"(r[1]), "=r"(r[2]), "=r"(r[3]) : "r"(addr));
}
__device__ __forceinline__ uint32_t smem_u32(const void* p) {
    uint32_t a;
    asm("{ .reg .u64 t; cvta.to.shared.u64 t, %1; cvt.u32.u64 %0, t; }" : "=r"(a) : "l"(p));
    return a;
}
__device__ __forceinline__ void cpasync16(uint32_t saddr, const void* gptr) {
    asm volatile("cp.async.ca.shared.global [%0], [%1], 16;" :: "r"(saddr), "l"(gptr));
}
#define CP_COMMIT() asm volatile("cp.async.commit_group;" ::: "memory")
#define CP_WAIT0()  asm volatile("cp.async.wait_group 0;" ::: "memory")

__device__ __forceinline__ void splitpack(float x, float y, uint32_t& hi, uint32_t& lo) {
    __nv_bfloat16 hx = __float2bfloat16_rn(x);
    __nv_bfloat16 hy = __float2bfloat16_rn(y);
    __nv_bfloat16 lx = __float2bfloat16_rn(x - __bfloat162float(hx));
    __nv_bfloat16 ly = __float2bfloat16_rn(y - __bfloat162float(hy));
    hi = (uint32_t)__bfloat16_as_ushort(hx) | ((uint32_t)__bfloat16_as_ushort(hy) << 16);
    lo = (uint32_t)__bfloat16_as_ushort(lx) | ((uint32_t)__bfloat16_as_ushort(ly) << 16);
}

// ================= weight repack: fp32 [K,N] -> n-major bf16 hi/lo tiles =================
__device__ __forceinline__ void repack_body(
    const float* __restrict__ W, __nv_bfloat16* __restrict__ Wh,
    __nv_bfloat16* __restrict__ Wl, int N, int KC, int kc, int nb)
{
    __shared__ unsigned char sh[TILE_B];
    __shared__ unsigned char sl[TILE_B];
    for (int e = threadIdx.x; e < 2048; e += 256) {
        int n_l = e & 63, k_l = e >> 6;
        float v = W[(long long)(kc * 32 + k_l) * N + nb * 64 + n_l];
        __nv_bfloat16 h = __float2bfloat16_rn(v);
        __nv_bfloat16 l = __float2bfloat16_rn(v - __bfloat162float(h));
        unsigned off = (unsigned)(n_l * 80 + k_l * 2);
        *(__nv_bfloat16*)(sh + off) = h;
        *(__nv_bfloat16*)(sl + off) = l;
    }
    __syncthreads();
    long long tb = ((long long)nb * KC + kc) * TILE_B;
    uint4* dh = (uint4*)((char*)Wh + tb);
    uint4* dl = (uint4*)((char*)Wl + tb);
    int t = threadIdx.x;
    dh[t] = ((uint4*)sh)[t];
    dl[t] = ((uint4*)sl)[t];
    if (t < 64) {
        dh[256 + t] = ((uint4*)sh)[256 + t];
        dl[256 + t] = ((uint4*)sl)[256 + t];
    }
}

__global__ __launch_bounds__(256) void repack_sq7(
    const float* w0, const float* w1, const float* w2, const float* w3,
    const float* w4, const float* w5, const float* w6,
    __nv_bfloat16* PH, __nv_bfloat16* PL)
{
    int z = blockIdx.z;
    const float* W = (z == 0) ? w0 : (z == 1) ? w1 : (z == 2) ? w2 :
                     (z == 3) ? w3 : (z == 4) ? w4 : (z == 5) ? w5 : w6;
    repack_body(W, PH + (long long)z * PK_SQ, PL + (long long)z * PK_SQ,
                DD, 32, blockIdx.x, blockIdx.y);
}
__global__ __launch_bounds__(256) void repack_w13(
    const float* w1, const float* w3, __nv_bfloat16* PH, __nv_bfloat16* PL)
{
    int z = blockIdx.z;
    repack_body(z ? w3 : w1, PH + OFF_W1 + (long long)z * PK_W13,
                PL + OFF_W1 + (long long)z * PK_W13, HID, 32, blockIdx.x, blockIdx.y);
}
__global__ __launch_bounds__(256) void repack_one(
    const float* W, __nv_bfloat16* Wh, __nv_bfloat16* Wl, int N)
{
    repack_body(W, Wh, Wl, N, gridDim.x, blockIdx.x, blockIdx.y);
}

// ================= mma.sync GEMM: CTA 128x64, 4 warps (warp 32x64), cp.async B =================
// (unchanged from R8 — verified)
#define SA_H 0
#define SA_L 10240
#define SB_H 20480
#define SB_L 25600
#define GBUF 30720

__global__ __launch_bounds__(128, 3) void mma_gemm(
    const float* __restrict__ A,
    const __nv_bfloat16* __restrict__ Bh0, const __nv_bfloat16* __restrict__ Bl0,
    const __nv_bfloat16* __restrict__ Bh1, const __nv_bfloat16* __restrict__ Bl1,
    const __nv_bfloat16* __restrict__ Bh2, const __nv_bfloat16* __restrict__ Bl2,
    float* __restrict__ C0, float* __restrict__ C1, float* __restrict__ C2,
    int Nper, int K, int nbper,
    long long a_bs, int a_off, int Mchunk,
    long long c_bs, int c_off, int acc)
{
    extern __shared__ __align__(16) unsigned char smem[];
    uint32_t sb = smem_u32(smem);

    int tid = threadIdx.x;
    int w = tid >> 5, lane = tid & 31;
    int g = lane >> 2, q = lane & 3;
    int rowin = lane & 7, l8 = (lane >> 3) & 1, l16 = (lane >> 4) & 1;

    int sel = blockIdx.x / nbper;
    int n_blk = blockIdx.x - sel * nbper;
    int block_n = n_blk * 64;
    int block_m = blockIdx.y * 128;
    const __nv_bfloat16* Bh = (sel == 0) ? Bh0 : ((sel == 1) ? Bh1 : Bh2);
    const __nv_bfloat16* Bl = (sel == 0) ? Bl0 : ((sel == 1) ? Bl1 : Bl2);
    float*               C  = (sel == 0) ? C0  : ((sel == 1) ? C1  : C2);

    int nk = K >> 5;

    const float* abase = A + (long long)(block_m / Mchunk) * a_bs
                       + (long long)((block_m % Mchunk) + a_off) * K;
    int r0 = tid >> 3, c4 = tid & 7;
    unsigned ast0 = (unsigned)(r0 * 80 + c4 * 8);

    const char* bh_src = (const char*)Bh + (long long)n_blk * nk * TILE_B;
    const char* bl_src = (const char*)Bl + (long long)n_blk * nk * TILE_B;

    unsigned a_frag_off[2];
    #pragma unroll
    for (int i = 0; i < 2; i++)
        a_frag_off[i] = (unsigned)((w * 32 + i * 16 + rowin + l8 * 8) * 80 + l16 * 16);
    unsigned b_frag_off[4];
    #pragma unroll
    for (int jp = 0; jp < 4; jp++)
        b_frag_off[jp] = (unsigned)((jp * 16 + rowin + l16 * 8) * 80 + l8 * 16);

    float c[2][8][4];
    #pragma unroll
    for (int i = 0; i < 2; i++)
        #pragma unroll
        for (int j = 0; j < 8; j++)
            #pragma unroll
            for (int e = 0; e < 4; e++) c[i][j][e] = 0.f;

    #define ISSUE_B(bufbase, chunk) do {                                          \
        long long _bo = (long long)(chunk) * TILE_B;                              \
        uint32_t _dh = sb + (bufbase) + SB_H;                                     \
        uint32_t _dl = sb + (bufbase) + SB_L;                                     \
        const char* _sh = bh_src + _bo;                                           \
        const char* _sl = bl_src + _bo;                                           \
        cpasync16(_dh + tid * 16, _sh + tid * 16);                                \
        cpasync16(_dh + (128 + tid) * 16, _sh + (128 + tid) * 16);                \
        cpasync16(_dl + tid * 16, _sl + tid * 16);                                \
        cpasync16(_dl + (128 + tid) * 16, _sl + (128 + tid) * 16);                \
        if (tid < 64) {                                                           \
            cpasync16(_dh + (256 + tid) * 16, _sh + (256 + tid) * 16);            \
            cpasync16(_dl + (256 + tid) * 16, _sl + (256 + tid) * 16);            \
        }                                                                         \
        CP_COMMIT();                                                              \
    } while (0)

    float4 pa[8];
    ISSUE_B(0, 0);
    #pragma unroll
    for (int j = 0; j < 8; j++)
        pa[j] = *(const float4*)(abase + (long long)(r0 + 16 * j) * K + c4 * 4);
    #pragma unroll
    for (int j = 0; j < 8; j++) {
        float4 v = pa[j];
        uint2 hv, lv;
        splitpack(v.x, v.y, hv.x, lv.x);
        splitpack(v.z, v.w, hv.y, lv.y);
        *(uint2*)(smem + SA_H + ast0 + j * (16 * 80)) = hv;
        *(uint2*)(smem + SA_L + ast0 + j * (16 * 80)) = lv;
    }
    CP_WAIT0();
    __syncthreads();

    int cur = 0;
    for (int it = 0; it < nk; it++) {
        bool hn = (it + 1 < nk);
        uint32_t nxtbase = (cur ^ 1) * GBUF;
        if (hn) {
            ISSUE_B(nxtbase, it + 1);
            #pragma unroll
            for (int j = 0; j < 8; j++)
                pa[j] = *(const float4*)(abase + (long long)(r0 + 16 * j) * K
                                         + (it + 1) * 32 + c4 * 4);
        }

        uint32_t abh = sb + cur * GBUF + SA_H;
        uint32_t abl = sb + cur * GBUF + SA_L;
        uint32_t bbh = sb + cur * GBUF + SB_H;
        uint32_t bbl = sb + cur * GBUF + SB_L;
        #pragma unroll
        for (int kk = 0; kk < 2; kk++) {
            int kb = kk * 32;
            uint32_t ah[2][4], al[2][4];
            #pragma unroll
            for (int i = 0; i < 2; i++) {
                ldsm4(ah[i], abh + a_frag_off[i] + kb);
                ldsm4(al[i], abl + a_frag_off[i] + kb);
            }
            #pragma unroll
            for (int jp = 0; jp < 4; jp++) {
                uint32_t bh[4], bl[4];
                ldsm4(bh, bbh + b_frag_off[jp] + kb);
                ldsm4(bl, bbl + b_frag_off[jp] + kb);
                #pragma unroll
                for (int i = 0; i < 2; i++) {
                    mma16816(c[i][jp*2],   ah[i], &bh[0]);
                    mma16816(c[i][jp*2],   ah[i], &bl[0]);
                    mma16816(c[i][jp*2],   al[i], &bh[0]);
                    mma16816(c[i][jp*2+1], ah[i], &bh[2]);
                    mma16816(c[i][jp*2+1], ah[i], &bl[2]);
                    mma16816(c[i][jp*2+1], al[i], &bh[2]);
                }
            }
        }

        if (hn) {
            #pragma unroll
            for (int j = 0; j < 8; j++) {
                float4 v = pa[j];
                uint2 hv, lv;
                splitpack(v.x, v.y, hv.x, lv.x);
                splitpack(v.z, v.w, hv.y, lv.y);
                *(uint2*)(smem + nxtbase + SA_H + ast0 + j * (16 * 80)) = hv;
                *(uint2*)(smem + nxtbase + SA_L + ast0 + j * (16 * 80)) = lv;
            }
            CP_WAIT0();
            __syncthreads();
            cur ^= 1;
        }
    }
    #undef ISSUE_B

    float* cbase = C + (long long)(block_m / Mchunk) * c_bs
                 + (long long)((block_m % Mchunk) + c_off) * Nper + block_n;
    #pragma unroll
    for (int i = 0; i < 2; i++) {
        #pragma unroll
        for (int half = 0; half < 2; half++) {
            int lrow = w * 32 + i * 16 + g + half * 8;
            float* crow = cbase + (long long)lrow * Nper;
            #pragma unroll
            for (int j = 0; j < 8; j++) {
                int col = j * 8 + 2 * q;
                float2 v;
                v.x = c[i][j][half * 2 + 0];
                v.y = c[i][j][half * 2 + 1];
                if (acc) {
                    float2 o = *(float2*)(crow + col);
                    v.x += o.x; v.y += o.y;
                }
                *(float2*)(crow + col) = v;
            }
        }
    }
}

// ---------------- RMSNorm ----------------
__global__ __launch_bounds__(256) void rmsnorm_kernel(
    const float* __restrict__ X, const float* __restrict__ W, float* __restrict__ O)
{
    int row = blockIdx.x;
    int t = threadIdx.x;
    const float4* x = (const float4*)(X + (long long)row * DD);
    float4 xv = x[t];
    float ss = xv.x*xv.x + xv.y*xv.y + xv.z*xv.z + xv.w*xv.w;
    #pragma unroll
    for (int off = 16; off >= 1; off >>= 1)
        ss += __shfl_xor_sync(0xffffffffu, ss, off);
    __shared__ float red[8];
    if ((t & 31) == 0) red[t >> 5] = ss;
    __syncthreads();
    __shared__ float s_inv;
    if (t == 0) {
        float tot = 0.f;
        #pragma unroll
        for (int i = 0; i < 8; i++) tot += red[i];
        s_inv = rsqrtf(tot * (1.0f / DD) + 1e-5f);
    }
    __syncthreads();
    float inv = s_inv;
    float4 wv = ((const float4*)W)[t];
    float4 ov = {xv.x*inv*wv.x, xv.y*inv*wv.y, xv.z*inv*wv.z, xv.w*inv*wv.w};
    ((float4*)(O + (long long)row * DD))[t] = ov;
}

// ---------------- SwiGLU ----------------
__global__ void silu_mul_kernel(float* __restrict__ h1, const float* __restrict__ h3, int n4)
{
    int i = blockIdx.x * blockDim.x + threadIdx.x;
    if (i >= n4) return;
    float4 a = ((float4*)h1)[i];
    float4 b = ((const float4*)h3)[i];
    a.x = a.x / (1.f + __expf(-a.x)) * b.x;
    a.y = a.y / (1.f + __expf(-a.y)) * b.y;
    a.z = a.z / (1.f + __expf(-a.z)) * b.z;
    a.w = a.w / (1.f + __expf(-a.w)) * b.w;
    ((float4*)h1)[i] = a;
}

// ---------------- RoPE (generic): pos = p0 + (row & (MM-1)) ----------------
__global__ void rope_kernel(float* __restrict__ T, const float* __restrict__ fcos,
                            const float* __restrict__ fsin,
                            int rows, long long bstride, int p0)
{
    int idx = blockIdx.x * blockDim.x + threadIdx.x;
    int total = BB * rows * HH * (HDIM / 2);
    if (idx >= total) return;
    int i = idx & 31;
    int h = (idx >> 5) & 15;
    int rest = idx >> 9;
    int lr = rest % rows;
    int b = rest / rows;
    int pos = p0 + (lr & (MM - 1));
    float* p = T + (long long)b * bstride + (long long)lr * DD + h * HDIM + 2 * i;
    float c = fcos[pos * 32 + i];
    float s = fsin[pos * 32 + i];
    float2 v = *(float2*)p;
    float2 o = {v.x * c - v.y * s, v.x * s + v.y * c};
    *(float2*)p = o;
}

// ---------------- Flash attention (dual-source K/V: mem buffer + X buffers) ----------------
#define AKH 0
#define AKL 9216
#define AVH 18432
#define AVL 27648

__global__ __launch_bounds__(128) void attn_mma(
    const float* __restrict__ XQ, const float* __restrict__ XK, const float* __restrict__ XV,
    const float* __restrict__ MK, const float* __restrict__ MV,
    float* __restrict__ Yg, int step)
{
    __shared__ __align__(16) unsigned char sm[36864];
    uint32_t sb = smem_u32(sm);

    int qt = blockIdx.x, h = blockIdx.y, b = blockIdx.z;
    int tid = threadIdx.x;
    int w = tid >> 5, lane = tid & 31;
    int g = lane >> 2, q = lane & 3;
    int m0 = w << 4;
    int rowin = lane & 7, l8 = (lane >> 3) & 1, l16 = (lane >> 4) & 1;

    int r  = tid >> 1;
    int ch = (tid & 1) << 5;

    unsigned koff[4], voff[4];
    #pragma unroll
    for (int jp = 0; jp < 4; jp++) {
        koff[jp] = (unsigned)((jp * 16 + l16 * 8 + rowin) * 144 + l8 * 16);
        voff[jp] = (unsigned)((l8 * 8 + rowin) * 144 + (jp * 16 + l16 * 8) * 2);
    }

    {
        const float* src = XQ + ((long long)b * SS + step * MM + qt * 64 + r) * DD + h * HDIM + ch;
        #pragma unroll
        for (int i = 0; i < 8; i++) {
            float4 v = *(const float4*)(src + i * 4);
            v.x *= 0.125f; v.y *= 0.125f; v.z *= 0.125f; v.w *= 0.125f;
            uint2 hv, lv;
            splitpack(v.x, v.y, hv.x, lv.x);
            splitpack(v.z, v.w, hv.y, lv.y);
            unsigned off = (unsigned)(r * 144 + (ch + i * 4) * 2);
            *(uint2*)(sm + AKH + off) = hv;
            *(uint2*)(sm + AKL + off) = lv;
        }
    }
    __syncthreads();
    uint32_t qh[4][4], ql[4][4];
    #pragma unroll
    for (int ks = 0; ks < 4; ks++) {
        int kb = ks * 32 + q * 4;
        int r0 = (m0 + g) * 144 + kb, r1 = r0 + 8 * 144;
        qh[ks][0] = *(const uint32_t*)(sm + AKH + r0);
        qh[ks][1] = *(const uint32_t*)(sm + AKH + r1);
        qh[ks][2] = *(const uint32_t*)(sm + AKH + r0 + 16);
        qh[ks][3] = *(const uint32_t*)(sm + AKH + r1 + 16);
        ql[ks][0] = *(const uint32_t*)(sm + AKL + r0);
        ql[ks][1] = *(const uint32_t*)(sm + AKL + r1);
        ql[ks][2] = *(const uint32_t*)(sm + AKL + r0 + 16);
        ql[ks][3] = *(const uint32_t*)(sm + AKL + r1 + 16);
    }

    float m_i[2] = {-1e30f, -1e30f}, l_i[2] = {0.f, 0.f};
    float o[8][4];
    #pragma unroll
    for (int j = 0; j < 8; j++)
        #pragma unroll
        for (int e = 0; e < 4; e++) o[j][e] = 0.f;

    int nkt = 9 + qt;
    for (int kt = 0; kt < nkt; kt++) {
        __syncthreads();

        const float* ksrc, * vsrc;
        if (kt < 8) {
            ksrc = MK + ((long long)b * MM + kt * 64 + r) * DD + h * HDIM + ch;
            vsrc = MV + ((long long)b * MM + kt * 64 + r) * DD + h * HDIM + ch;
        } else {
            long long base = (long long)b * SS + step * MM + (kt - 8) * 64 + r;
            ksrc = XK + base * DD + h * HDIM + ch;
            vsrc = XV + base * DD + h * HDIM + ch;
        }
        #pragma unroll
        for (int i = 0; i < 8; i++) {
            unsigned off = (unsigned)(r * 144 + (ch + i * 4) * 2);
            float4 kv = *(const float4*)(ksrc + i * 4);
            uint2 hv, lv;
            splitpack(kv.x, kv.y, hv.x, lv.x);
            splitpack(kv.z, kv.w, hv.y, lv.y);
            *(uint2*)(sm + AKH + off) = hv;
            *(uint2*)(sm + AKL + off) = lv;

            float4 vv = *(const float4*)(vsrc + i * 4);
            splitpack(vv.x, vv.y, hv.x, lv.x);
            splitpack(vv.z, vv.w, hv.y, lv.y);
            *(uint2*)(sm + AVH + off) = hv;
            *(uint2*)(sm + AVL + off) = lv;
        }
        __syncthreads();

        float s[8][4];
        #pragma unroll
        for (int j = 0; j < 8; j++)
            #pragma unroll
            for (int e = 0; e < 4; e++) s[j][e] = 0.f;

        #pragma unroll
        for (int ks = 0; ks < 4; ks++) {
            #pragma unroll
            for (int jp = 0; jp < 4; jp++) {
                uint32_t bh[4], bl[4];
                ldsm4(bh, sb + AKH + koff[jp] + ks * 32);
                ldsm4(bl, sb + AKL + koff[jp] + ks * 32);
                mma16816(s[jp*2],   qh[ks], &bh[0]);
                mma16816(s[jp*2],   qh[ks], &bl[0]);
                mma16816(s[jp*2],   ql[ks], &bh[0]);
                mma16816(s[jp*2+1], qh[ks], &bh[2]);
                mma16816(s[jp*2+1], qh[ks], &bl[2]);
                mma16816(s[jp*2+1], ql[ks], &bh[2]);
            }
        }

        if (kt == nkt - 1) {
            #pragma unroll
            for (int j = 0; j < 8; j++)
                #pragma unroll
                for (int e = 0; e < 4; e++) {
                    int col = j * 8 + 2 * q + (e & 1);
                    int row = m0 + g + ((e >> 1) << 3);
                    if (col > row) s[j][e] = -1e30f;
                }
        }

        float mx0 = -1e30f, mx1 = -1e30f;
        #pragma unroll
        for (int j = 0; j < 8; j++) {
            mx0 = fmaxf(mx0, fmaxf(s[j][0], s[j][1]));
            mx1 = fmaxf(mx1, fmaxf(s[j][2], s[j][3]));
        }
        mx0 = fmaxf(mx0, __shfl_xor_sync(0xffffffffu, mx0, 1));
        mx0 = fmaxf(mx0, __shfl_xor_sync(0xffffffffu, mx0, 2));
        mx1 = fmaxf(mx1, __shfl_xor_sync(0xffffffffu, mx1, 1));
        mx1 = fmaxf(mx1, __shfl_xor_sync(0xffffffffu, mx1, 2));
        float mn0 = fmaxf(m_i[0], mx0), mn1 = fmaxf(m_i[1], mx1);
        float al0 = __expf(m_i[0] - mn0), al1 = __expf(m_i[1] - mn1);
        float sum0 = 0.f, sum1 = 0.f;
        #pragma unroll
        for (int j = 0; j < 8; j++) {
            s[j][0] = __expf(s[j][0] - mn0);
            s[j][1] = __expf(s[j][1] - mn0);
            s[j][2] = __expf(s[j][2] - mn1);
            s[j][3] = __expf(s[j][3] - mn1);
            sum0 += s[j][0] + s[j][1];
            sum1 += s[j][2] + s[j][3];
        }
        sum0 += __shfl_xor_sync(0xffffffffu, sum0, 1);
        sum0 += __shfl_xor_sync(0xffffffffu, sum0, 2);
        sum1 += __shfl_xor_sync(0xffffffffu, sum1, 1);
        sum1 += __shfl_xor_sync(0xffffffffu, sum1, 2);
        l_i[0] = l_i[0] * al0 + sum0;  m_i[0] = mn0;
        l_i[1] = l_i[1] * al1 + sum1;  m_i[1] = mn1;
        #pragma unroll
        for (int j = 0; j < 8; j++) {
            o[j][0] *= al0; o[j][1] *= al0;
            o[j][2] *= al1; o[j][3] *= al1;
        }

        #pragma unroll
        for (int ks = 0; ks < 4; ks++) {
            uint32_t pah[4], pal[4];
            splitpack(s[2*ks][0],   s[2*ks][1],   pah[0], pal[0]);
            splitpack(s[2*ks][2],   s[2*ks][3],   pah[1], pal[1]);
            splitpack(s[2*ks+1][0], s[2*ks+1][1], pah[2], pal[2]);
            splitpack(s[2*ks+1][2], s[2*ks+1][3], pah[3], pal[3]);
            #pragma unroll
            for (int jp = 0; jp < 4; jp++) {
                uint32_t vh[4], vl[4];
                ldsm4t(vh, sb + AVH + voff[jp] + ks * 2304);
                ldsm4t(vl, sb + AVL + voff[jp] + ks * 2304);
                mma16816(o[jp*2],   pah, &vh[0]);
                mma16816(o[jp*2],   pah, &vl[0]);
                mma16816(o[jp*2],   pal, &vh[0]);
                mma16816(o[jp*2+1], pah, &vh[2]);
                mma16816(o[jp*2+1], pah, &vl[2]);
                mma16816(o[jp*2+1], pal, &vh[2]);
            }
        }
    }

    float inv0 = 1.f / l_i[0], inv1 = 1.f / l_i[1];
    float* ybase = Yg + ((long long)b * SS + step * MM + qt * 64) * DD + h * HDIM;
    #pragma unroll
    for (int j = 0; j < 8; j++) {
        int col = j * 8 + 2 * q;
        float2 v0 = {o[j][0] * inv0, o[j][1] * inv0};
        float2 v1 = {o[j][2] * inv1, o[j][3] * inv1};
        *(float2*)(ybase + (long long)(m0 + g) * DD + col)     = v0;
        *(float2*)(ybase + (long long)(m0 + g + 8) * DD + col) = v1;
    }
}

// ---------------- host orchestration ----------------
static void launch_tc(const float* A,
                      const __nv_bfloat16* h0, const __nv_bfloat16* l0,
                      const __nv_bfloat16* h1, const __nv_bfloat16* l1,
                      const __nv_bfloat16* h2, const __nv_bfloat16* l2,
                      float* C0, float* C1, float* C2,
                      int nsub, int Mtot, int Nper, int K,
                      long long a_bs, int a_off, int Mchunk,
                      long long c_bs, int c_off, int acc)
{
    int nbper = Nper / 64;
    dim3 grid(nsub * nbper, Mtot / 128);
    mma_gemm<<<grid, 128, 2 * GBUF>>>(A, h0, l0, h1, l1, h2, l2, C0, C1, C2,
                                      Nper, K, nbper, a_bs, a_off, Mchunk, c_bs, c_off, acc);
}

extern "C" void kernel_launch(void* const* d_in, const int* in_sizes, int n_in,
                              void* d_out, int out_size)
{
    const float* x     = (const float*)d_in[0];
    const float* fcos  = (const float*)d_in[1];
    const float* fsin  = (const float*)d_in[2];
    const float* wq    = (const float*)d_in[3];
    const float* wk    = (const float*)d_in[4];
    const float* wv    = (const float*)d_in[5];
    const float* wo    = (const float*)d_in[6];
    const float* wm    = (const float*)d_in[7];
    const float* wkm   = (const float*)d_in[8];
    const float* wvm   = (const float*)d_in[9];
    const float* w1    = (const float*)d_in[10];
    const float* w3    = (const float*)d_in[11];
    const float* w2    = (const float*)d_in[12];
    const float* ffn_w = (const float*)d_in[13];
    const float* mem_w = (const float*)d_in[14];
    const float* omem  = (const float*)d_in[15];
    float* out = (float*)d_out;

    cudaFuncSetAttribute(mma_gemm, cudaFuncAttributeMaxDynamicSharedMemorySize, 2 * GBUF);

    float *Y, *XQ, *XK, *XV, *MK, *MV, *OM2, *HN, *H1, *H3, *OMN;
    __nv_bfloat16 *PH, *PL;
    cudaGetSymbolAddress((void**)&Y,   g_Y);
    cudaGetSymbolAddress((void**)&XQ,  g_XQ);
    cudaGetSymbolAddress((void**)&XK,  g_XK);
    cudaGetSymbolAddress((void**)&XV,  g_XV);
    cudaGetSymbolAddress((void**)&MK,  g_MK);
    cudaGetSymbolAddress((void**)&MV,  g_MV);
    cudaGetSymbolAddress((void**)&OM2, g_OM2);
    cudaGetSymbolAddress((void**)&HN,  g_HN);
    cudaGetSymbolAddress((void**)&H1,  g_H1);
    cudaGetSymbolAddress((void**)&H3,  g_H3);
    cudaGetSymbolAddress((void**)&OMN, g_OMN);
    cudaGetSymbolAddress((void**)&PH,  g_pk_hi);
    cudaGetSymbolAddress((void**)&PL,  g_pk_lo);

    // repack weights (3 launches)
    repack_sq7<<<dim3(32, 16, 7), 256>>>(wq, wk, wv, wm, wkm, wvm, wo, PH, PL);
    repack_w13<<<dim3(32, 44, 2), 256>>>(w1, w3, PH, PL);
    repack_one<<<dim3(88, 16), 256>>>(w2, PH + OFF_W2, PL + OFF_W2, DD);

    const long long XBS = (long long)SS * DD;
    const long long MBS = (long long)MM * DD;

    // ---- hoisted: QKV for ALL steps (8192 rows, one 3-output GEMM) ----
    launch_tc(x, PH+OFF_WQ, PL+OFF_WQ, PH+OFF_WK, PL+OFF_WK, PH+OFF_WV, PL+OFF_WV,
              XQ, XK, XV, 3, BB*SS, DD, DD, 0, 0, BB*SS, 0, 0, 0);
    // global RoPE on XQ/XK: pos = M + (row mod M)
    {
        int tot = BB * SS * HH * 32;
        rope_kernel<<<(tot + 255) / 256, 256>>>(XQ, fcos, fsin, SS, XBS, MM);
        rope_kernel<<<(tot + 255) / 256, 256>>>(XK, fcos, fsin, SS, XBS, MM);
    }

    for (int step = 0; step < NSTEP; step++) {
        // om @ wm  (step 0: origin_mem broadcast via a_bs=0)
        if (step == 0)
            launch_tc(omem, PH+OFF_WM, PL+OFF_WM, 0,0, 0,0, OM2, 0, 0, 1,
                      BB*MM, DD, DD, 0, 0, MM, MBS, 0, 0);
        else
            launch_tc(Y, PH+OFF_WM, PL+OFF_WM, 0,0, 0,0, OM2, 0, 0, 1,
                      BB*MM, DD, DD, XBS, (step-1)*MM, MM, MBS, 0, 0);

        rmsnorm_kernel<<<BB*MM, 256>>>(OM2, ffn_w, HN);
        launch_tc(HN, PH+OFF_W1, PL+OFF_W1, PH+OFF_W3, PL+OFF_W3, 0,0,
                  H1, H3, 0, 2, BB*MM, HID, DD, 0, 0, BB*MM, 0, 0, 0);
        {
            int n4 = BB * MM * HID / 4;
            silu_mul_kernel<<<(n4 + 255) / 256, 256>>>(H1, H3, n4);
        }
        launch_tc(H1, PH+OFF_W2, PL+OFF_W2, 0,0, 0,0, OM2, 0, 0, 1,
                  BB*MM, DD, HID, 0, 0, BB*MM, 0, 0, 1);

        rmsnorm_kernel<<<BB*MM, 256>>>(OM2, mem_w, OMN);

        // mk/mv (flat BB*MM rows)
        launch_tc(OMN, PH+OFF_WKM, PL+OFF_WKM, PH+OFF_WVM, PL+OFF_WVM, 0,0,
                  MK, MV, 0, 2, BB*MM, DD, DD, 0, 0, BB*MM, 0, 0, 0);

        // RoPE mem-K: positions 0..M-1
        {
            int tot = BB * MM * HH * 32;
            rope_kernel<<<(tot + 255) / 256, 256>>>(MK, fcos, fsin, MM, MBS, 0);
        }

        attn_mma<<<dim3(8, HH, BB), 128>>>(XQ, XK, XV, MK, MV, Y, step);
    }

    // final projection: out = Y @ wo
    launch_tc(Y, PH+OFF_WO, PL+OFF_WO, 0,0, 0,0, out, 0, 0, 1,
              BB*SS, DD, DD, 0, 0, BB*SS, 0, 0, 0);
}

// round 13
// speedup vs baseline: 1.2376x; 1.0112x over previous
#include <cuda_runtime.h>
#include <cuda_bf16.h>
#include <math.h>
#include <stdint.h>

// Problem constants
#define BB 2
#define SS 4096
#define DD 1024
#define HH 16
#define HDIM 64
#define MM 512
#define LL 1024
#define HID 2816
#define NSTEP 8

// ---------------- scratch (device globals; no allocation allowed) ----------------
__device__ float g_Y  [BB * SS * DD];
__device__ float g_XQ [BB * SS * DD];
__device__ float g_XK [BB * SS * DD];
__device__ float g_XV [BB * SS * DD];
__device__ float g_MKa[BB * MM * DD];
__device__ float g_MKb[BB * MM * DD];
__device__ float g_MVa[BB * MM * DD];
__device__ float g_MVb[BB * MM * DD];
__device__ float g_P0 [BB * MM * DD];
__device__ float g_P1 [BB * MM * DD];
__device__ float g_OM2[BB * MM * DD];
__device__ float g_HN [BB * MM * DD];
__device__ float g_H1 [BB * MM * HID];
__device__ float g_H3 [BB * MM * HID];
__device__ float g_H1b[BB * MM * HID];
__device__ float g_H3b[BB * MM * HID];
__device__ float g_OMN[BB * MM * DD];

// packed bf16 hi/lo weight tiles: (n_blk 64 x k_chunk 32), n-major, 80B row stride.
#define TILE_B 5120
#define PK_SQ  (512 * 2560)
#define PK_W13 (1408 * 2560)
#define PK_W2  (1408 * 2560)
#define PK_TOTAL (7*PK_SQ + 2*PK_W13 + PK_W2)
__device__ __align__(256) __nv_bfloat16 g_pk_hi[PK_TOTAL];
__device__ __align__(256) __nv_bfloat16 g_pk_lo[PK_TOTAL];

#define OFF_WQ  0
#define OFF_WK  (1*PK_SQ)
#define OFF_WV  (2*PK_SQ)
#define OFF_WM  (3*PK_SQ)
#define OFF_WKM (4*PK_SQ)
#define OFF_WVM (5*PK_SQ)
#define OFF_WO  (6*PK_SQ)
#define OFF_W1  (7*PK_SQ)
#define OFF_W3  (7*PK_SQ + PK_W13)
#define OFF_W2  (7*PK_SQ + 2*PK_W13)

// ---------------- mma / ldmatrix / cp.async helpers (baseline PTX) ----------------
__device__ __forceinline__ void mma16816(float* c, const uint32_t* a, const uint32_t* b) {
    asm volatile(
        "mma.sync.aligned.m16n8k16.row.col.f32.bf16.bf16.f32 "
        "{%0,%1,%2,%3}, {%4,%5,%6,%7}, {%8,%9}, {%0,%1,%2,%3};"
        : "+f"(c[0]), "+f"(c[1]), "+f"(c[2]), "+f"(c[3])
        : "r"(a[0]), "r"(a[1]), "r"(a[2]), "r"(a[3]), "r"(b[0]), "r"(b[1]));
}
__device__ __forceinline__ void ldsm4(uint32_t* r, uint32_t addr) {
    asm volatile("ldmatrix.sync.aligned.m8n8.x4.shared.b16 {%0,%1,%2,%3}, [%4];"
        : "=r"(r[0]), "=r"(r[1]), "=r"(r[2]), "=r"(r[3]) : "r"(addr));
}
__device__ __forceinline__ void ldsm4t(uint32_t* r, uint32_t addr) {
    asm volatile("ldmatrix.sync.aligned.m8n8.x4.trans.shared.b16 {%0,%1,%2,%3}, [%4];"
        : "=r"(r[0]), "=r"(r[1]), "=r"(r[2]), "=r"(r[3]) : "r"(addr));
}
__device__ __forceinline__ uint32_t smem_u32(const void* p) {
    uint32_t a;
    asm("{ .reg .u64 t; cvta.to.shared.u64 t, %1; cvt.u32.u64 %0, t; }" : "=r"(a) : "l"(p));
    return a;
}
__device__ __forceinline__ void cpasync16(uint32_t saddr, const void* gptr) {
    asm volatile("cp.async.ca.shared.global [%0], [%1], 16;" :: "r"(saddr), "l"(gptr));
}
#define CP_COMMIT() asm volatile("cp.async.commit_group;" ::: "memory")
#define CP_WAIT0()  asm volatile("cp.async.wait_group 0;" ::: "memory")

__device__ __forceinline__ void splitpack(float x, float y, uint32_t& hi, uint32_t& lo) {
    __nv_bfloat16 hx = __float2bfloat16_rn(x);
    __nv_bfloat16 hy = __float2bfloat16_rn(y);
    __nv_bfloat16 lx = __float2bfloat16_rn(x - __bfloat162float(hx));
    __nv_bfloat16 ly = __float2bfloat16_rn(y - __bfloat162float(hy));
    hi = (uint32_t)__bfloat16_as_ushort(hx) | ((uint32_t)__bfloat16_as_ushort(hy) << 16);
    lo = (uint32_t)__bfloat16_as_ushort(lx) | ((uint32_t)__bfloat16_as_ushort(ly) << 16);
}

// ================= weight repack =================
__device__ __forceinline__ void repack_body(
    const float* __restrict__ W, __nv_bfloat16* __restrict__ Wh,
    __nv_bfloat16* __restrict__ Wl, int N, int KC, int kc, int nb)
{
    __shared__ unsigned char sh[TILE_B];
    __shared__ unsigned char sl[TILE_B];
    for (int e = threadIdx.x; e < 2048; e += 256) {
        int n_l = e & 63, k_l = e >> 6;
        float v = W[(long long)(kc * 32 + k_l) * N + nb * 64 + n_l];
        __nv_bfloat16 h = __float2bfloat16_rn(v);
        __nv_bfloat16 l = __float2bfloat16_rn(v - __bfloat162float(h));
        unsigned off = (unsigned)(n_l * 80 + k_l * 2);
        *(__nv_bfloat16*)(sh + off) = h;
        *(__nv_bfloat16*)(sl + off) = l;
    }
    __syncthreads();
    long long tb = ((long long)nb * KC + kc) * TILE_B;
    uint4* dh = (uint4*)((char*)Wh + tb);
    uint4* dl = (uint4*)((char*)Wl + tb);
    int t = threadIdx.x;
    dh[t] = ((uint4*)sh)[t];
    dl[t] = ((uint4*)sl)[t];
    if (t < 64) {
        dh[256 + t] = ((uint4*)sh)[256 + t];
        dl[256 + t] = ((uint4*)sl)[256 + t];
    }
}

__global__ __launch_bounds__(256) void repack_sq7(
    const float* w0, const float* w1, const float* w2, const float* w3,
    const float* w4, const float* w5, const float* w6,
    __nv_bfloat16* PH, __nv_bfloat16* PL)
{
    int z = blockIdx.z;
    const float* W = (z == 0) ? w0 : (z == 1) ? w1 : (z == 2) ? w2 :
                     (z == 3) ? w3 : (z == 4) ? w4 : (z == 5) ? w5 : w6;
    repack_body(W, PH + (long long)z * PK_SQ, PL + (long long)z * PK_SQ,
                DD, 32, blockIdx.x, blockIdx.y);
}
__global__ __launch_bounds__(256) void repack_w13(
    const float* w1, const float* w3, __nv_bfloat16* PH, __nv_bfloat16* PL)
{
    int z = blockIdx.z;
    repack_body(z ? w3 : w1, PH + OFF_W1 + (long long)z * PK_W13,
                PL + OFF_W1 + (long long)z * PK_W13, HID, 32, blockIdx.x, blockIdx.y);
}
__global__ __launch_bounds__(256) void repack_one(
    const float* W, __nv_bfloat16* Wh, __nv_bfloat16* Wl, int N)
{
    repack_body(W, Wh, Wl, N, gridDim.x, blockIdx.x, blockIdx.y);
}

// ================= mma.sync GEMM with optional K-split (grid.z) =================
#define SA_H 0
#define SA_L 10240
#define SB_H 20480
#define SB_L 25600
#define GBUF 30720

__global__ __launch_bounds__(128, 3) void mma_gemm(
    const float* __restrict__ A,
    const __nv_bfloat16* __restrict__ Bh0, const __nv_bfloat16* __restrict__ Bl0,
    const __nv_bfloat16* __restrict__ Bh1, const __nv_bfloat16* __restrict__ Bl1,
    const __nv_bfloat16* __restrict__ Bh2, const __nv_bfloat16* __restrict__ Bl2,
    float* __restrict__ C0, float* __restrict__ C1, float* __restrict__ C2,
    float* __restrict__ C0z, float* __restrict__ C1z,
    int Nper, int KCtot, int nkc, int nbper,
    long long a_bs, int a_off, int Mchunk,
    long long c_bs, int c_off, int acc)
{
    extern __shared__ __align__(16) unsigned char smem[];
    uint32_t sb = smem_u32(smem);

    int tid = threadIdx.x;
    int w = tid >> 5, lane = tid & 31;
    int g = lane >> 2, q = lane & 3;
    int rowin = lane & 7, l8 = (lane >> 3) & 1, l16 = (lane >> 4) & 1;

    int sel = blockIdx.x / nbper;
    int n_blk = blockIdx.x - sel * nbper;
    int block_n = n_blk * 64;
    int block_m = blockIdx.y * 128;
    int kc0 = blockIdx.z * nkc;
    const __nv_bfloat16* Bh = (sel == 0) ? Bh0 : ((sel == 1) ? Bh1 : Bh2);
    const __nv_bfloat16* Bl = (sel == 0) ? Bl0 : ((sel == 1) ? Bl1 : Bl2);
    float* C = blockIdx.z ? ((sel == 0) ? C0z : C1z)
                          : ((sel == 0) ? C0 : ((sel == 1) ? C1 : C2));

    const float* abase = A + (long long)(block_m / Mchunk) * a_bs
                       + (long long)((block_m % Mchunk) + a_off) * (KCtot * 32);
    int r0 = tid >> 3, c4 = tid & 7;
    unsigned ast0 = (unsigned)(r0 * 80 + c4 * 8);

    const char* bh_src = (const char*)Bh + (long long)n_blk * KCtot * TILE_B;
    const char* bl_src = (const char*)Bl + (long long)n_blk * KCtot * TILE_B;

    unsigned a_frag_off[2];
    #pragma unroll
    for (int i = 0; i < 2; i++)
        a_frag_off[i] = (unsigned)((w * 32 + i * 16 + rowin + l8 * 8) * 80 + l16 * 16);
    unsigned b_frag_off[4];
    #pragma unroll
    for (int jp = 0; jp < 4; jp++)
        b_frag_off[jp] = (unsigned)((jp * 16 + rowin + l16 * 8) * 80 + l8 * 16);

    float c[2][8][4];
    #pragma unroll
    for (int i = 0; i < 2; i++)
        #pragma unroll
        for (int j = 0; j < 8; j++)
            #pragma unroll
            for (int e = 0; e < 4; e++) c[i][j][e] = 0.f;

    #define ISSUE_B(bufbase, kc) do {                                             \
        long long _bo = (long long)(kc) * TILE_B;                                 \
        uint32_t _dh = sb + (bufbase) + SB_H;                                     \
        uint32_t _dl = sb + (bufbase) + SB_L;                                     \
        const char* _sh = bh_src + _bo;                                           \
        const char* _sl = bl_src + _bo;                                           \
        cpasync16(_dh + tid * 16, _sh + tid * 16);                                \
        cpasync16(_dh + (128 + tid) * 16, _sh + (128 + tid) * 16);                \
        cpasync16(_dl + tid * 16, _sl + tid * 16);                                \
        cpasync16(_dl + (128 + tid) * 16, _sl + (128 + tid) * 16);                \
        if (tid < 64) {                                                           \
            cpasync16(_dh + (256 + tid) * 16, _sh + (256 + tid) * 16);            \
            cpasync16(_dl + (256 + tid) * 16, _sl + (256 + tid) * 16);            \
        }                                                                         \
        CP_COMMIT();                                                              \
    } while (0)

    float4 pa[8];
    ISSUE_B(0, kc0);
    #pragma unroll
    for (int j = 0; j < 8; j++)
        pa[j] = *(const float4*)(abase + (long long)(r0 + 16 * j) * (KCtot * 32)
                                 + kc0 * 32 + c4 * 4);
    #pragma unroll
    for (int j = 0; j < 8; j++) {
        float4 v = pa[j];
        uint2 hv, lv;
        splitpack(v.x, v.y, hv.x, lv.x);
        splitpack(v.z, v.w, hv.y, lv.y);
        *(uint2*)(smem + SA_H + ast0 + j * (16 * 80)) = hv;
        *(uint2*)(smem + SA_L + ast0 + j * (16 * 80)) = lv;
    }
    CP_WAIT0();
    __syncthreads();

    int cur = 0;
    for (int it = 0; it < nkc; it++) {
        bool hn = (it + 1 < nkc);
        uint32_t nxtbase = (cur ^ 1) * GBUF;
        if (hn) {
            ISSUE_B(nxtbase, kc0 + it + 1);
            #pragma unroll
            for (int j = 0; j < 8; j++)
                pa[j] = *(const float4*)(abase + (long long)(r0 + 16 * j) * (KCtot * 32)
                                         + (kc0 + it + 1) * 32 + c4 * 4);
        }

        uint32_t abh = sb + cur * GBUF + SA_H;
        uint32_t abl = sb + cur * GBUF + SA_L;
        uint32_t bbh = sb + cur * GBUF + SB_H;
        uint32_t bbl = sb + cur * GBUF + SB_L;
        #pragma unroll
        for (int kk = 0; kk < 2; kk++) {
            int kb = kk * 32;
            uint32_t ah[2][4], al[2][4];
            #pragma unroll
            for (int i = 0; i < 2; i++) {
                ldsm4(ah[i], abh + a_frag_off[i] + kb);
                ldsm4(al[i], abl + a_frag_off[i] + kb);
            }
            #pragma unroll
            for (int jp = 0; jp < 4; jp++) {
                uint32_t bh[4], bl[4];
                ldsm4(bh, bbh + b_frag_off[jp] + kb);
                ldsm4(bl, bbl + b_frag_off[jp] + kb);
                #pragma unroll
                for (int i = 0; i < 2; i++) {
                    mma16816(c[i][jp*2],   ah[i], &bh[0]);
                    mma16816(c[i][jp*2],   ah[i], &bl[0]);
                    mma16816(c[i][jp*2],   al[i], &bh[0]);
                    mma16816(c[i][jp*2+1], ah[i], &bh[2]);
                    mma16816(c[i][jp*2+1], ah[i], &bl[2]);
                    mma16816(c[i][jp*2+1], al[i], &bh[2]);
                }
            }
        }

        if (hn) {
            #pragma unroll
            for (int j = 0; j < 8; j++) {
                float4 v = pa[j];
                uint2 hv, lv;
                splitpack(v.x, v.y, hv.x, lv.x);
                splitpack(v.z, v.w, hv.y, lv.y);
                *(uint2*)(smem + nxtbase + SA_H + ast0 + j * (16 * 80)) = hv;
                *(uint2*)(smem + nxtbase + SA_L + ast0 + j * (16 * 80)) = lv;
            }
            CP_WAIT0();
            __syncthreads();
            cur ^= 1;
        }
    }
    #undef ISSUE_B

    float* cbase = C + (long long)(block_m / Mchunk) * c_bs
                 + (long long)((block_m % Mchunk) + c_off) * Nper + block_n;
    #pragma unroll
    for (int i = 0; i < 2; i++) {
        #pragma unroll
        for (int half = 0; half < 2; half++) {
            int lrow = w * 32 + i * 16 + g + half * 8;
            float* crow = cbase + (long long)lrow * Nper;
            #pragma unroll
            for (int j = 0; j < 8; j++) {
                int col = j * 8 + 2 * q;
                float2 v;
                v.x = c[i][j][half * 2 + 0];
                v.y = c[i][j][half * 2 + 1];
                if (acc) {
                    float2 o = *(float2*)(crow + col);
                    v.x += o.x; v.y += o.y;
                }
                *(float2*)(crow + col) = v;
            }
        }
    }
}

// ---------------- RMSNorm variants ----------------
__device__ __forceinline__ float block_rms_inv(float ss) {
    #pragma unroll
    for (int off = 16; off >= 1; off >>= 1)
        ss += __shfl_xor_sync(0xffffffffu, ss, off);
    __shared__ float red[8];
    int t = threadIdx.x;
    if ((t & 31) == 0) red[t >> 5] = ss;
    __syncthreads();
    __shared__ float s_inv;
    if (t == 0) {
        float tot = 0.f;
        #pragma unroll
        for (int i = 0; i < 8; i++) tot += red[i];
        s_inv = rsqrtf(tot * (1.0f / DD) + 1e-5f);
    }
    __syncthreads();
    return s_inv;
}

__global__ __launch_bounds__(256) void rmsnorm_sum2_kernel(
    const float* __restrict__ Xa, const float* __restrict__ Xb,
    const float* __restrict__ W, float* __restrict__ O, float* __restrict__ OS)
{
    long long base = (long long)blockIdx.x * DD;
    int t = threadIdx.x;
    float4 a = ((const float4*)(Xa + base))[t];
    float4 b = ((const float4*)(Xb + base))[t];
    float4 v = {a.x + b.x, a.y + b.y, a.z + b.z, a.w + b.w};
    ((float4*)(OS + base))[t] = v;
    float inv = block_rms_inv(v.x*v.x + v.y*v.y + v.z*v.z + v.w*v.w);
    float4 wv = ((const float4*)W)[t];
    float4 ov = {v.x*inv*wv.x, v.y*inv*wv.y, v.z*inv*wv.z, v.w*inv*wv.w};
    ((float4*)(O + base))[t] = ov;
}

__global__ __launch_bounds__(256) void rmsnorm_sum3_kernel(
    const float* __restrict__ Xa, const float* __restrict__ Xb, const float* __restrict__ Xc,
    const float* __restrict__ W, float* __restrict__ O)
{
    long long base = (long long)blockIdx.x * DD;
    int t = threadIdx.x;
    float4 a = ((const float4*)(Xa + base))[t];
    float4 b = ((const float4*)(Xb + base))[t];
    float4 cc = ((const float4*)(Xc + base))[t];
    float4 v = {a.x + b.x + cc.x, a.y + b.y + cc.y, a.z + b.z + cc.z, a.w + b.w + cc.w};
    float inv = block_rms_inv(v.x*v.x + v.y*v.y + v.z*v.z + v.w*v.w);
    float4 wv = ((const float4*)W)[t];
    float4 ov = {v.x*inv*wv.x, v.y*inv*wv.y, v.z*inv*wv.z, v.w*inv*wv.w};
    ((float4*)(O + base))[t] = ov;
}

__global__ void silu_sum_kernel(
    float* __restrict__ h1a, const float* __restrict__ h1b,
    const float* __restrict__ h3a, const float* __restrict__ h3b, int n4)
{
    int i = blockIdx.x * blockDim.x + threadIdx.x;
    if (i >= n4) return;
    float4 a0 = ((const float4*)h1a)[i];
    float4 a1 = ((const float4*)h1b)[i];
    float4 b0 = ((const float4*)h3a)[i];
    float4 b1 = ((const float4*)h3b)[i];
    float4 a = {a0.x + a1.x, a0.y + a1.y, a0.z + a1.z, a0.w + a1.w};
    float4 b = {b0.x + b1.x, b0.y + b1.y, b0.z + b1.z, b0.w + b1.w};
    a.x = a.x / (1.f + __expf(-a.x)) * b.x;
    a.y = a.y / (1.f + __expf(-a.y)) * b.y;
    a.z = a.z / (1.f + __expf(-a.z)) * b.z;
    a.w = a.w / (1.f + __expf(-a.w)) * b.w;
    ((float4*)h1a)[i] = a;
}

__global__ void rope_kernel(float* __restrict__ T, const float* __restrict__ fcos,
                            const float* __restrict__ fsin,
                            int rows, long long bstride, int p0)
{
    int idx = blockIdx.x * blockDim.x + threadIdx.x;
    int total = BB * rows * HH * (HDIM / 2);
    if (idx >= total) return;
    int i = idx & 31;
    int h = (idx >> 5) & 15;
    int rest = idx >> 9;
    int lr = rest % rows;
    int b = rest / rows;
    int pos = p0 + (lr & (MM - 1));
    float* p = T + (long long)b * bstride + (long long)lr * DD + h * HDIM + 2 * i;
    float c = fcos[pos * 32 + i];
    float s = fsin[pos * 32 + i];
    float2 v = *(float2*)p;
    float2 o = {v.x * c - v.y * s, v.x * s + v.y * c};
    *(float2*)p = o;
}

// ---------------- Flash attention: mem K/V from split partials, rope fused ----------------
#define AKH 0
#define AKL 9216
#define AVH 18432
#define AVL 27648

__global__ __launch_bounds__(128) void attn_mma(
    const float* __restrict__ XQ, const float* __restrict__ XK, const float* __restrict__ XV,
    const float* __restrict__ MKa, const float* __restrict__ MKb,
    const float* __restrict__ MVa, const float* __restrict__ MVb,
    const float* __restrict__ fcos, const float* __restrict__ fsin,
    float* __restrict__ Yg, int step)
{
    __shared__ __align__(16) unsigned char sm[36864];
    uint32_t sb = smem_u32(sm);

    int qt = blockIdx.x, h = blockIdx.y, b = blockIdx.z;
    int tid = threadIdx.x;
    int w = tid >> 5, lane = tid & 31;
    int g = lane >> 2, q = lane & 3;
    int m0 = w << 4;
    int rowin = lane & 7, l8 = (lane >> 3) & 1, l16 = (lane >> 4) & 1;

    int r  = tid >> 1;
    int ch = (tid & 1) << 5;

    unsigned koff[4], voff[4];
    #pragma unroll
    for (int jp = 0; jp < 4; jp++) {
        koff[jp] = (unsigned)((jp * 16 + l16 * 8 + rowin) * 144 + l8 * 16);
        voff[jp] = (unsigned)((l8 * 8 + rowin) * 144 + (jp * 16 + l16 * 8) * 2);
    }

    {
        const float* src = XQ + ((long long)b * SS + step * MM + qt * 64 + r) * DD + h * HDIM + ch;
        #pragma unroll
        for (int i = 0; i < 8; i++) {
            float4 v = *(const float4*)(src + i * 4);
            v.x *= 0.125f; v.y *= 0.125f; v.z *= 0.125f; v.w *= 0.125f;
            uint2 hv, lv;
            splitpack(v.x, v.y, hv.x, lv.x);
            splitpack(v.z, v.w, hv.y, lv.y);
            unsigned off = (unsigned)(r * 144 + (ch + i * 4) * 2);
            *(uint2*)(sm + AKH + off) = hv;
            *(uint2*)(sm + AKL + off) = lv;
        }
    }
    __syncthreads();
    uint32_t qh[4][4], ql[4][4];
    #pragma unroll
    for (int ks = 0; ks < 4; ks++) {
        int kb = ks * 32 + q * 4;
        int r0 = (m0 + g) * 144 + kb, r1 = r0 + 8 * 144;
        qh[ks][0] = *(const uint32_t*)(sm + AKH + r0);
        qh[ks][1] = *(const uint32_t*)(sm + AKH + r1);
        qh[ks][2] = *(const uint32_t*)(sm + AKH + r0 + 16);
        qh[ks][3] = *(const uint32_t*)(sm + AKH + r1 + 16);
        ql[ks][0] = *(const uint32_t*)(sm + AKL + r0);
        ql[ks][1] = *(const uint32_t*)(sm + AKL + r1);
        ql[ks][2] = *(const uint32_t*)(sm + AKL + r0 + 16);
        ql[ks][3] = *(const uint32_t*)(sm + AKL + r1 + 16);
    }

    float m_i[2] = {-1e30f, -1e30f}, l_i[2] = {0.f, 0.f};
    float o[8][4];
    #pragma unroll
    for (int j = 0; j < 8; j++)
        #pragma unroll
        for (int e = 0; e < 4; e++) o[j][e] = 0.f;

    int nkt = 9 + qt;
    for (int kt = 0; kt < nkt; kt++) {
        __syncthreads();

        if (kt < 8) {
            long long goff = ((long long)b * MM + kt * 64 + r) * DD + h * HDIM + ch;
            int pos = kt * 64 + r;
            #pragma unroll
            for (int i = 0; i < 8; i++) {
                unsigned off = (unsigned)(r * 144 + (ch + i * 4) * 2);
                float4 ka = *(const float4*)(MKa + goff + i * 4);
                float4 kb2 = *(const float4*)(MKb + goff + i * 4);
                float kx = ka.x + kb2.x, ky = ka.y + kb2.y;
                float kz = ka.z + kb2.z, kw = ka.w + kb2.w;
                int ip = (ch >> 1) + 2 * i;
                float2 cs = *(const float2*)(fcos + pos * 32 + ip);
                float2 sn = *(const float2*)(fsin + pos * 32 + ip);
                float x0 = kx * cs.x - ky * sn.x;
                float y0 = kx * sn.x + ky * cs.x;
                float x1 = kz * cs.y - kw * sn.y;
                float y1 = kz * sn.y + kw * cs.y;
                uint2 hv, lv;
                splitpack(x0, y0, hv.x, lv.x);
                splitpack(x1, y1, hv.y, lv.y);
                *(uint2*)(sm + AKH + off) = hv;
                *(uint2*)(sm + AKL + off) = lv;

                float4 va = *(const float4*)(MVa + goff + i * 4);
                float4 vb = *(const float4*)(MVb + goff + i * 4);
                splitpack(va.x + vb.x, va.y + vb.y, hv.x, lv.x);
                splitpack(va.z + vb.z, va.w + vb.w, hv.y, lv.y);
                *(uint2*)(sm + AVH + off) = hv;
                *(uint2*)(sm + AVL + off) = lv;
            }
        } else {
            long long base = (long long)b * SS + step * MM + (kt - 8) * 64 + r;
            const float* ksrc = XK + base * DD + h * HDIM + ch;
            const float* vsrc = XV + base * DD + h * HDIM + ch;
            #pragma unroll
            for (int i = 0; i < 8; i++) {
                unsigned off = (unsigned)(r * 144 + (ch + i * 4) * 2);
                float4 kv = *(const float4*)(ksrc + i * 4);
                uint2 hv, lv;
                splitpack(kv.x, kv.y, hv.x, lv.x);
                splitpack(kv.z, kv.w, hv.y, lv.y);
                *(uint2*)(sm + AKH + off) = hv;
                *(uint2*)(sm + AKL + off) = lv;

                float4 vv = *(const float4*)(vsrc + i * 4);
                splitpack(vv.x, vv.y, hv.x, lv.x);
                splitpack(vv.z, vv.w, hv.y, lv.y);
                *(uint2*)(sm + AVH + off) = hv;
                *(uint2*)(sm + AVL + off) = lv;
            }
        }
        __syncthreads();

        float s[8][4];
        #pragma unroll
        for (int j = 0; j < 8; j++)
            #pragma unroll
            for (int e = 0; e < 4; e++) s[j][e] = 0.f;

        #pragma unroll
        for (int ks = 0; ks < 4; ks++) {
            #pragma unroll
            for (int jp = 0; jp < 4; jp++) {
                uint32_t bh[4], bl[4];
                ldsm4(bh, sb + AKH + koff[jp] + ks * 32);
                ldsm4(bl, sb + AKL + koff[jp] + ks * 32);
                mma16816(s[jp*2],   qh[ks], &bh[0]);
                mma16816(s[jp*2],   qh[ks], &bl[0]);
                mma16816(s[jp*2],   ql[ks], &bh[0]);
                mma16816(s[jp*2+1], qh[ks], &bh[2]);
                mma16816(s[jp*2+1], qh[ks], &bl[2]);
                mma16816(s[jp*2+1], ql[ks], &bh[2]);
            }
        }

        if (kt == nkt - 1) {
            #pragma unroll
            for (int j = 0; j < 8; j++)
                #pragma unroll
                for (int e = 0; e < 4; e++) {
                    int col = j * 8 + 2 * q + (e & 1);
                    int row = m0 + g + ((e >> 1) << 3);
                    if (col > row) s[j][e] = -1e30f;
                }
        }

        float mx0 = -1e30f, mx1 = -1e30f;
        #pragma unroll
        for (int j = 0; j < 8; j++) {
            mx0 = fmaxf(mx0, fmaxf(s[j][0], s[j][1]));
            mx1 = fmaxf(mx1, fmaxf(s[j][2], s[j][3]));
        }
        mx0 = fmaxf(mx0, __shfl_xor_sync(0xffffffffu, mx0, 1));
        mx0 = fmaxf(mx0, __shfl_xor_sync(0xffffffffu, mx0, 2));
        mx1 = fmaxf(mx1, __shfl_xor_sync(0xffffffffu, mx1, 1));
        mx1 = fmaxf(mx1, __shfl_xor_sync(0xffffffffu, mx1, 2));
        float mn0 = fmaxf(m_i[0], mx0), mn1 = fmaxf(m_i[1], mx1);
        float al0 = __expf(m_i[0] - mn0), al1 = __expf(m_i[1] - mn1);
        float sum0 = 0.f, sum1 = 0.f;
        #pragma unroll
        for (int j = 0; j < 8; j++) {
            s[j][0] = __expf(s[j][0] - mn0);
            s[j][1] = __expf(s[j][1] - mn0);
            s[j][2] = __expf(s[j][2] - mn1);
            s[j][3] = __expf(s[j][3] - mn1);
            sum0 += s[j][0] + s[j][1];
            sum1 += s[j][2] + s[j][3];
        }
        sum0 += __shfl_xor_sync(0xffffffffu, sum0, 1);
        sum0 += __shfl_xor_sync(0xffffffffu, sum0, 2);
        sum1 += __shfl_xor_sync(0xffffffffu, sum1, 1);
        sum1 += __shfl_xor_sync(0xffffffffu, sum1, 2);
        l_i[0] = l_i[0] * al0 + sum0;  m_i[0] = mn0;
        l_i[1] = l_i[1] * al1 + sum1;  m_i[1] = mn1;
        #pragma unroll
        for (int j = 0; j < 8; j++) {
            o[j][0] *= al0; o[j][1] *= al0;
            o[j][2] *= al1; o[j][3] *= al1;
        }

        #pragma unroll
        for (int ks = 0; ks < 4; ks++) {
            uint32_t pah[4], pal[4];
            splitpack(s[2*ks][0],   s[2*ks][1],   pah[0], pal[0]);
            splitpack(s[2*ks][2],   s[2*ks][3],   pah[1], pal[1]);
            splitpack(s[2*ks+1][0], s[2*ks+1][1], pah[2], pal[2]);
            splitpack(s[2*ks+1][2], s[2*ks+1][3], pah[3], pal[3]);
            #pragma unroll
            for (int jp = 0; jp < 4; jp++) {
                uint32_t vh[4], vl[4];
                ldsm4t(vh, sb + AVH + voff[jp] + ks * 2304);
                ldsm4t(vl, sb + AVL + voff[jp] + ks * 2304);
                mma16816(o[jp*2],   pah, &vh[0]);
                mma16816(o[jp*2],   pah, &vl[0]);
                mma16816(o[jp*2],   pal, &vh[0]);
                mma16816(o[jp*2+1], pah, &vh[2]);
                mma16816(o[jp*2+1], pah, &vl[2]);
                mma16816(o[jp*2+1], pal, &vh[2]);
            }
        }
    }

    float inv0 = 1.f / l_i[0], inv1 = 1.f / l_i[1];
    float* ybase = Yg + ((long long)b * SS + step * MM + qt * 64) * DD + h * HDIM;
    #pragma unroll
    for (int j = 0; j < 8; j++) {
        int col = j * 8 + 2 * q;
        float2 v0 = {o[j][0] * inv0, o[j][1] * inv0};
        float2 v1 = {o[j][2] * inv1, o[j][3] * inv1};
        *(float2*)(ybase + (long long)(m0 + g) * DD + col)     = v0;
        *(float2*)(ybase + (long long)(m0 + g + 8) * DD + col) = v1;
    }
}

// ---------------- host orchestration ----------------
static void launch_tc(const float* A,
                      const __nv_bfloat16* h0, const __nv_bfloat16* l0,
                      const __nv_bfloat16* h1, const __nv_bfloat16* l1,
                      const __nv_bfloat16* h2, const __nv_bfloat16* l2,
                      float* C0, float* C1, float* C2, float* C0z, float* C1z,
                      int nsub, int ksplit, int Mtot, int Nper, int K,
                      long long a_bs, int a_off, int Mchunk,
                      long long c_bs, int c_off, int acc)
{
    int nbper = Nper / 64;
    int KCtot = K / 32;
    int nz = ksplit ? 2 : 1;
    dim3 grid(nsub * nbper, Mtot / 128, nz);
    mma_gemm<<<grid, 128, 2 * GBUF>>>(A, h0, l0, h1, l1, h2, l2,
                                      C0, C1, C2, C0z, C1z,
                                      Nper, KCtot, KCtot / nz, nbper,
                                      a_bs, a_off, Mchunk, c_bs, c_off, acc);
}

extern "C" void kernel_launch(void* const* d_in, const int* in_sizes, int n_in,
                              void* d_out, int out_size)
{
    const float* x     = (const float*)d_in[0];
    const float* fcos  = (const float*)d_in[1];
    const float* fsin  = (const float*)d_in[2];
    const float* wq    = (const float*)d_in[3];
    const float* wk    = (const float*)d_in[4];
    const float* wv    = (const float*)d_in[5];
    const float* wo    = (const float*)d_in[6];
    const float* wm    = (const float*)d_in[7];
    const float* wkm   = (const float*)d_in[8];
    const float* wvm   = (const float*)d_in[9];
    const float* w1    = (const float*)d_in[10];
    const float* w3    = (const float*)d_in[11];
    const float* w2    = (const float*)d_in[12];
    const float* ffn_w = (const float*)d_in[13];
    const float* mem_w = (const float*)d_in[14];
    const float* omem  = (const float*)d_in[15];
    float* out = (float*)d_out;

    cudaFuncSetAttribute(mma_gemm, cudaFuncAttributeMaxDynamicSharedMemorySize, 2 * GBUF);

    float *Y, *XQ, *XK, *XV, *MKa, *MKb, *MVa, *MVb, *P0, *P1;
    float *OM2, *HN, *H1, *H3, *H1b, *H3b, *OMN;
    __nv_bfloat16 *PH, *PL;
    cudaGetSymbolAddress((void**)&Y,   g_Y);
    cudaGetSymbolAddress((void**)&XQ,  g_XQ);
    cudaGetSymbolAddress((void**)&XK,  g_XK);
    cudaGetSymbolAddress((void**)&XV,  g_XV);
    cudaGetSymbolAddress((void**)&MKa, g_MKa);
    cudaGetSymbolAddress((void**)&MKb, g_MKb);
    cudaGetSymbolAddress((void**)&MVa, g_MVa);
    cudaGetSymbolAddress((void**)&MVb, g_MVb);
    cudaGetSymbolAddress((void**)&P0,  g_P0);
    cudaGetSymbolAddress((void**)&P1,  g_P1);
    cudaGetSymbolAddress((void**)&OM2, g_OM2);
    cudaGetSymbolAddress((void**)&HN,  g_HN);
    cudaGetSymbolAddress((void**)&H1,  g_H1);
    cudaGetSymbolAddress((void**)&H3,  g_H3);
    cudaGetSymbolAddress((void**)&H1b, g_H1b);
    cudaGetSymbolAddress((void**)&H3b, g_H3b);
    cudaGetSymbolAddress((void**)&OMN, g_OMN);
    cudaGetSymbolAddress((void**)&PH,  g_pk_hi);
    cudaGetSymbolAddress((void**)&PL,  g_pk_lo);

    // repack weights (3 launches)
    repack_sq7<<<dim3(32, 16, 7), 256>>>(wq, wk, wv, wm, wkm, wvm, wo, PH, PL);
    repack_w13<<<dim3(32, 44, 2), 256>>>(w1, w3, PH, PL);
    repack_one<<<dim3(88, 16), 256>>>(w2, PH + OFF_W2, PL + OFF_W2, DD);

    const long long XBS = (long long)SS * DD;
    const long long MBS = (long long)MM * DD;

    // ---- hoisted QKV for all steps + global RoPE ----
    launch_tc(x, PH+OFF_WQ, PL+OFF_WQ, PH+OFF_WK, PL+OFF_WK, PH+OFF_WV, PL+OFF_WV,
              XQ, XK, XV, 0, 0, 3, 0, BB*SS, DD, DD, 0, 0, BB*SS, 0, 0, 0);
    {
        int tot = BB * SS * HH * 32;
        rope_kernel<<<(tot + 255) / 256, 256>>>(XQ, fcos, fsin, SS, XBS, MM);
        rope_kernel<<<(tot + 255) / 256, 256>>>(XK, fcos, fsin, SS, XBS, MM);
    }

    for (int step = 0; step < NSTEP; step++) {
        // om @ wm (split-K2 -> P0,P1); c_bs = MBS maps batch rows into flat P buffers
        if (step == 0)
            launch_tc(omem, PH+OFF_WM, PL+OFF_WM, 0,0, 0,0, P0, 0, 0, P1, 0,
                      1, 1, BB*MM, DD, DD, 0, 0, MM, MBS, 0, 0);
        else
            launch_tc(Y, PH+OFF_WM, PL+OFF_WM, 0,0, 0,0, P0, 0, 0, P1, 0,
                      1, 1, BB*MM, DD, DD, XBS, (step-1)*MM, MM, MBS, 0, 0);

        // HN = rms(P0+P1)*ffn_w ; OM2 = P0+P1
        rmsnorm_sum2_kernel<<<BB*MM, 256>>>(P0, P1, ffn_w, HN, OM2);

        // w1/w3 (split-K2, 1408 CTAs)
        launch_tc(HN, PH+OFF_W1, PL+OFF_W1, PH+OFF_W3, PL+OFF_W3, 0,0,
                  H1, H3, 0, H1b, H3b, 2, 1, BB*MM, HID, DD, 0, 0, BB*MM, 0, 0, 0);
        {
            int n4 = BB * MM * HID / 4;
            silu_sum_kernel<<<(n4 + 255) / 256, 256>>>(H1, H1b, H3, H3b, n4);
        }

        // w2 (split-K2 over K=2816 -> P0,P1)
        launch_tc(H1, PH+OFF_W2, PL+OFF_W2, 0,0, 0,0, P0, 0, 0, P1, 0,
                  1, 1, BB*MM, DD, HID, 0, 0, BB*MM, 0, 0, 0);

        // OMN = rms(OM2 + P0 + P1)*mem_w
        rmsnorm_sum3_kernel<<<BB*MM, 256>>>(OM2, P0, P1, mem_w, OMN);

        // mk/mv (split-K2, 512 CTAs) -> partials; rope+sum fused in attention
        launch_tc(OMN, PH+OFF_WKM, PL+OFF_WKM, PH+OFF_WVM, PL+OFF_WVM, 0,0,
                  MKa, MVa, 0, MKb, MVb, 2, 1, BB*MM, DD, DD, 0, 0, BB*MM, 0, 0, 0);

        attn_mma<<<dim3(8, HH, BB), 128>>>(XQ, XK, XV, MKa, MKb, MVa, MVb,
                                           fcos, fsin, Y, step);
    }

    // final projection: out = Y @ wo
    launch_tc(Y, PH+OFF_WO, PL+OFF_WO, 0,0, 0,0, out, 0, 0, 0, 0,
              1, 0, BB*SS, DD, DD, 0, 0, BB*SS, 0, 0, 0);
}